// round 9
// baseline (speedup 1.0000x reference)
#include <cuda_runtime.h>
#include <cstdint>
#include <math.h>

// ---------------- problem constants ----------------
#define HD     1024
#define FOURH  4096
#define BATCH  2048
#define SEQ    24
#define EDIM   256
#define VOCAB  37
#define MROWS  (BATCH*SEQ)   // 49152

// ---------------- device scratch (no allocation allowed) ----------------
__device__ float g_Xg[(size_t)MROWS * FOURH];      // 805 MB : per-layer input projections (gate-interleaved cols)
__device__ float g_y[(size_t)MROWS * HD];          // 201 MB : per-layer outputs (tf32-rounded)
__device__ float g_state[(size_t)6 * BATCH * HD];  // h0a,h0b,c0,h1a,h1b,c1
__device__ float g_wperm[(size_t)2*4096*256 + (size_t)6*4096*1024]; // 109 MB permuted+rounded weights
__device__ float g_bsum[4 * FOURH];                // merged permuted biases per layer
__device__ float g_embr[VOCAB * EDIM];             // tf32-rounded embedding
__device__ int   g_dectok[BATCH * SEQ];

// ---------------- small helpers ----------------
__device__ __forceinline__ float tf32r(float x) {
    uint32_t r;
    asm("cvt.rna.tf32.f32 %0, %1;" : "=r"(r) : "f"(x));
    return __uint_as_float(r);
}

__device__ __forceinline__ void mma_tf32(float* c, const uint32_t* a, const uint32_t* b) {
    asm volatile(
        "mma.sync.aligned.m16n8k8.row.col.f32.tf32.tf32.f32 "
        "{%0,%1,%2,%3}, {%4,%5,%6,%7}, {%8,%9}, {%0,%1,%2,%3};\n"
        : "+f"(c[0]), "+f"(c[1]), "+f"(c[2]), "+f"(c[3])
        : "r"(a[0]), "r"(a[1]), "r"(a[2]), "r"(a[3]), "r"(b[0]), "r"(b[1]));
}

__device__ __forceinline__ void cp16(void* s, const void* g) {
    uint32_t sa = (uint32_t)__cvta_generic_to_shared(s);
    asm volatile("cp.async.ca.shared.global [%0], [%1], 16;\n" :: "r"(sa), "l"(g));
}
#define CP_COMMIT() asm volatile("cp.async.commit_group;\n" ::)
#define CP_WAIT(n)  asm volatile("cp.async.wait_group %0;\n" :: "n"(n))

__device__ __forceinline__ float sigf(float x) { return 1.f / (1.f + expf(-x)); }

// ---------------- GEMM: C[M,4096] = A[M,K] @ Wp[4096,K]^T (+ fused epilogue) ----------------
// Weights are gate-interleaved: permuted row r' = 4u+g  (orig row g*1024+u), so output
// columns come as [i f g o] per hidden unit. All MMA operands are pre-rounded to tf32.
// MODE 0: input projection.  A row m = (tok ? embr[tok[m]] : A[m]).  C = acc + bsum (permuted).
// MODE 1: recurrent step + fused LSTM cell.  A = h_read.  gates = acc + Xg[(m*SEQ+t)*4096+col];
//         c updated in-place; new h (tf32-rounded) written to hW (ping-pong buffer, NOT the
//         buffer being read -> no cross-block read/write race) and optionally y[m*SEQ+t].
constexpr int BM = 128, BN = 128, BK = 16, SPAD = 4;  // smem stride 20 floats -> conflict-free

template<int MODE>
__global__ __launch_bounds__(256, 2)
void gemm_tf32(const float* __restrict__ A, const int* __restrict__ tok,
               const float* __restrict__ W,
               const float* __restrict__ bsum,
               const float* __restrict__ Xg,
               float* __restrict__ C,          // MODE0: Xg out
               float* __restrict__ hW, float* __restrict__ cP,  // MODE1
               float* __restrict__ yP, int writeY,
               int K, int t)
{
    __shared__ float sA[2][BM][BK + SPAD];
    __shared__ float sB[2][BN][BK + SPAD];

    const int tid  = threadIdx.x;
    const int bm   = blockIdx.y * BM;
    const int bn   = blockIdx.x * BN;
    const int ldr  = tid >> 2;          // 0..63
    const int ldc  = (tid & 3) * 4;     // 0,4,8,12

    // loader base pointers (token gather folded in)
    const float* abase[2];
    const float* bbase[2];
#pragma unroll
    for (int i = 0; i < 2; ++i) {
        int m = bm + ldr + i * 64;
        const float* base = tok ? (A + (size_t)tok[m] * K) : (A + (size_t)m * K);
        abase[i] = base + ldc;
        bbase[i] = W + (size_t)(bn + ldr + i * 64) * K + ldc;
    }

    const int KT = K / BK;

    // prologue: stage 0 and 1
#pragma unroll
    for (int i = 0; i < 2; ++i) cp16(&sA[0][ldr + i * 64][ldc], abase[i]);
#pragma unroll
    for (int i = 0; i < 2; ++i) cp16(&sB[0][ldr + i * 64][ldc], bbase[i]);
    CP_COMMIT();
#pragma unroll
    for (int i = 0; i < 2; ++i) cp16(&sA[1][ldr + i * 64][ldc], abase[i] + BK);
#pragma unroll
    for (int i = 0; i < 2; ++i) cp16(&sB[1][ldr + i * 64][ldc], bbase[i] + BK);
    CP_COMMIT();
    CP_WAIT(1);
    __syncthreads();

    const int wid  = tid >> 5;
    const int lane = tid & 31;
    const int wm   = (wid >> 2) * 64;   // warp M offset (0 or 64)
    const int wn   = (wid & 3) * 32;    // warp N offset (0,32,64,96)
    const int lr   = lane >> 2;         // 0..7
    const int lc   = lane & 3;          // 0..3

    float acc[4][4][4];
#pragma unroll
    for (int a = 0; a < 4; ++a)
#pragma unroll
        for (int b = 0; b < 4; ++b)
#pragma unroll
            for (int q = 0; q < 4; ++q) acc[a][b][q] = 0.f;

    for (int kt = 0; kt < KT; ++kt) {
        const int buf = kt & 1;
#pragma unroll
        for (int ks = 0; ks < 2; ++ks) {
            const int k0 = ks * 8;
            uint32_t af[4][4], bf[4][2];
#pragma unroll
            for (int mt = 0; mt < 4; ++mt) {
                int r = wm + mt * 16 + lr;
                af[mt][0] = __float_as_uint(sA[buf][r][k0 + lc]);
                af[mt][1] = __float_as_uint(sA[buf][r + 8][k0 + lc]);
                af[mt][2] = __float_as_uint(sA[buf][r][k0 + lc + 4]);
                af[mt][3] = __float_as_uint(sA[buf][r + 8][k0 + lc + 4]);
            }
#pragma unroll
            for (int nt = 0; nt < 4; ++nt) {
                int n = wn + nt * 8 + lr;
                bf[nt][0] = __float_as_uint(sB[buf][n][k0 + lc]);
                bf[nt][1] = __float_as_uint(sB[buf][n][k0 + lc + 4]);
            }
#pragma unroll
            for (int mt = 0; mt < 4; ++mt)
#pragma unroll
                for (int nt = 0; nt < 4; ++nt)
                    mma_tf32(acc[mt][nt], af[mt], bf[nt]);
        }
        __syncthreads();                 // everyone done reading buf
        if (kt + 2 < KT) {
#pragma unroll
            for (int i = 0; i < 2; ++i) cp16(&sA[buf][ldr + i * 64][ldc], abase[i] + (kt + 2) * BK);
#pragma unroll
            for (int i = 0; i < 2; ++i) cp16(&sB[buf][ldr + i * 64][ldc], bbase[i] + (kt + 2) * BK);
            CP_COMMIT();
        }
        if (kt + 1 < KT) {
            if (kt + 2 < KT) { CP_WAIT(1); } else { CP_WAIT(0); }
            __syncthreads();
        }
    }

    // ---------------- epilogue ----------------
#pragma unroll
    for (int mt = 0; mt < 4; ++mt) {
        const int gr0 = bm + wm + mt * 16 + lr;
        const int gr1 = gr0 + 8;
#pragma unroll
        for (int nt = 0; nt < 4; ++nt) {
            const int gc = bn + wn + nt * 8 + lc * 2;
            if (MODE == 0) {
                float bx = bsum[gc], by = bsum[gc + 1];
                float2 v0, v1;
                v0.x = acc[mt][nt][0] + bx; v0.y = acc[mt][nt][1] + by;
                v1.x = acc[mt][nt][2] + bx; v1.y = acc[mt][nt][3] + by;
                *(float2*)&C[(size_t)gr0 * FOURH + gc] = v0;
                *(float2*)&C[(size_t)gr1 * FOURH + gc] = v1;
            } else {
                // gates = acc + Xg ;  columns interleaved: even lc -> (i,f), odd lc -> (g,o)
                float2 x0 = *(const float2*)&Xg[((size_t)gr0 * SEQ + t) * FOURH + gc];
                float2 x1 = *(const float2*)&Xg[((size_t)gr1 * SEQ + t) * FOURH + gc];
                float v0 = acc[mt][nt][0] + x0.x;  // row gr0, col gc
                float v1 = acc[mt][nt][1] + x0.y;  // row gr0, col gc+1
                float v2 = acc[mt][nt][2] + x1.x;  // row gr1, col gc
                float v3 = acc[mt][nt][3] + x1.y;  // row gr1, col gc+1
                float p0 = __shfl_xor_sync(0xffffffffu, v0, 1);
                float p1 = __shfl_xor_sync(0xffffffffu, v1, 1);
                float p2 = __shfl_xor_sync(0xffffffffu, v2, 1);
                float p3 = __shfl_xor_sync(0xffffffffu, v3, 1);
                if ((lane & 1) == 0) {
                    // this lane holds (i,f); partner supplied (g,o)
                    const int u = gc >> 2;
                    const size_t cb0 = (size_t)gr0 * HD + u;
                    const size_t cb1 = (size_t)gr1 * HD + u;
                    float c0 = cP[cb0], c1 = cP[cb1];
                    c0 = sigf(v1) * c0 + sigf(v0) * tanhf(p0);
                    c1 = sigf(v3) * c1 + sigf(v2) * tanhf(p2);
                    float h0 = sigf(p1) * tanhf(c0);
                    float h1 = sigf(p3) * tanhf(c1);
                    cP[cb0] = c0; cP[cb1] = c1;
                    h0 = tf32r(h0); h1 = tf32r(h1);
                    hW[cb0] = h0; hW[cb1] = h1;
                    if (writeY) {
                        yP[((size_t)gr0 * SEQ + t) * HD + u] = h0;
                        yP[((size_t)gr1 * SEQ + t) * HD + u] = h1;
                    }
                }
            }
        }
    }
}

// ---------------- setup kernels ----------------
// permute rows g*1024+u -> 4u+g, round to tf32
__global__ void permW_k(const float* __restrict__ in, float* __restrict__ out, int K)
{
    int idx = blockIdx.x * blockDim.x + threadIdx.x;
    if (idx < FOURH * K) {
        int rp = idx / K, k = idx - rp * K;
        int orig = (rp & 3) * HD + (rp >> 2);
        out[idx] = tf32r(in[orig * K + k]);
    }
}

__global__ void permB_k(const float* bi0, const float* bh0, const float* bi1, const float* bh1,
                        const float* bi2, const float* bh2, const float* bi3, const float* bh3,
                        float* __restrict__ out)
{
    int idx = blockIdx.x * blockDim.x + threadIdx.x;   // over 4*4096
    if (idx < 4 * FOURH) {
        int l = idx >> 12, rp = idx & (FOURH - 1);
        int orig = (rp & 3) * HD + (rp >> 2);
        const float* bi = (l == 0) ? bi0 : (l == 1) ? bi1 : (l == 2) ? bi2 : bi3;
        const float* bh = (l == 0) ? bh0 : (l == 1) ? bh1 : (l == 2) ? bh2 : bh3;
        out[idx] = bi[orig] + bh[orig];
    }
}

__global__ void embr_k(const float* __restrict__ emb, float* __restrict__ out)
{
    int i = blockIdx.x * blockDim.x + threadIdx.x;
    if (i < VOCAB * EDIM) out[i] = tf32r(emb[i]);
}

__global__ void zero_k(float* p, int n4)
{
    int i = blockIdx.x * blockDim.x + threadIdx.x;
    if (i < n4) ((float4*)p)[i] = make_float4(0.f, 0.f, 0.f, 0.f);
}

__global__ void build_dectok_k(const int* __restrict__ tgt, int* __restrict__ dt)
{
    int idx = blockIdx.x * blockDim.x + threadIdx.x;
    if (idx < BATCH * SEQ) {
        int b = idx / SEQ, t = idx - b * SEQ;
        dt[idx] = (t == 0) ? 1 : tgt[b * SEQ + t - 1];
    }
}

// ---------------- output projection: out[M,37] = y[M,1024] @ fcW[37,1024]^T + fcb ----------------
__global__ __launch_bounds__(256)
void proj_k(const float* __restrict__ y, const float* __restrict__ fcW,
            const float* __restrict__ fcb, float* __restrict__ out)
{
    __shared__ float ys[128][65];
    __shared__ float ws[40][65];
    const int tid = threadIdx.x;
    const int gm0 = blockIdx.x * 128;
    const int r0  = (tid >> 3) * 4;
    const int n0  = (tid & 7) * 5;

    float acc[4][5];
#pragma unroll
    for (int i = 0; i < 4; ++i)
#pragma unroll
        for (int j = 0; j < 5; ++j) acc[i][j] = 0.f;

    for (int kc = 0; kc < 16; ++kc) {
        __syncthreads();
        for (int i = tid; i < 128 * 16; i += 256) {
            int r = i >> 4, c4 = (i & 15) * 4;
            float4 v = *(const float4*)&y[(size_t)(gm0 + r) * HD + kc * 64 + c4];
            ys[r][c4] = v.x; ys[r][c4 + 1] = v.y; ys[r][c4 + 2] = v.z; ys[r][c4 + 3] = v.w;
        }
        for (int i = tid; i < 40 * 64; i += 256) {
            int n = i >> 6, cc = i & 63;
            ws[n][cc] = (n < VOCAB) ? fcW[n * HD + kc * 64 + cc] : 0.f;
        }
        __syncthreads();
#pragma unroll 8
        for (int k = 0; k < 64; ++k) {
            float yv[4], wv[5];
#pragma unroll
            for (int i = 0; i < 4; ++i) yv[i] = ys[r0 + i][k];
#pragma unroll
            for (int j = 0; j < 5; ++j) wv[j] = ws[n0 + j][k];
#pragma unroll
            for (int i = 0; i < 4; ++i)
#pragma unroll
                for (int j = 0; j < 5; ++j) acc[i][j] += yv[i] * wv[j];
        }
    }
#pragma unroll
    for (int i = 0; i < 4; ++i)
#pragma unroll
        for (int j = 0; j < 5; ++j) {
            int n = n0 + j;
            if (n < VOCAB)
                out[(size_t)(gm0 + r0 + i) * VOCAB + n] = acc[i][j] + fcb[n];
        }
}

// ---------------- host driver ----------------
extern "C" void kernel_launch(void* const* d_in, const int* in_sizes, int n_in,
                              void* d_out, int out_size)
{
    const int*   src    = (const int*)d_in[0];
    const int*   tgt    = (const int*)d_in[1];
    const float* emb    = (const float*)d_in[2];
    const float* eW_ih0 = (const float*)d_in[3];
    const float* eW_hh0 = (const float*)d_in[4];
    const float* eb_ih0 = (const float*)d_in[5];
    const float* eb_hh0 = (const float*)d_in[6];
    const float* eW_ih1 = (const float*)d_in[7];
    const float* eW_hh1 = (const float*)d_in[8];
    const float* eb_ih1 = (const float*)d_in[9];
    const float* eb_hh1 = (const float*)d_in[10];
    const float* dW_ih0 = (const float*)d_in[11];
    const float* dW_hh0 = (const float*)d_in[12];
    const float* db_ih0 = (const float*)d_in[13];
    const float* db_hh0 = (const float*)d_in[14];
    const float* dW_ih1 = (const float*)d_in[15];
    const float* dW_hh1 = (const float*)d_in[16];
    const float* db_ih1 = (const float*)d_in[17];
    const float* db_hh1 = (const float*)d_in[18];
    const float* fcW    = (const float*)d_in[19];
    const float* fcb    = (const float*)d_in[20];
    float* out = (float*)d_out;

    float *Xg, *y, *state, *wperm, *bsum, *embr;
    int*   dectok;
    cudaGetSymbolAddress((void**)&Xg,     g_Xg);
    cudaGetSymbolAddress((void**)&y,      g_y);
    cudaGetSymbolAddress((void**)&state,  g_state);
    cudaGetSymbolAddress((void**)&wperm,  g_wperm);
    cudaGetSymbolAddress((void**)&bsum,   g_bsum);
    cudaGetSymbolAddress((void**)&embr,   g_embr);
    cudaGetSymbolAddress((void**)&dectok, g_dectok);

    // h ping-pong buffers + c per layer chain
    float* h0buf[2] = { state,
                        state + (size_t)1 * BATCH * HD };
    float* c0      =   state + (size_t)2 * BATCH * HD;
    float* h1buf[2] = { state + (size_t)3 * BATCH * HD,
                        state + (size_t)4 * BATCH * HD };
    float* c1      =   state + (size_t)5 * BATCH * HD;

    // permuted weight layout inside g_wperm
    size_t off = 0;
    float* eWih0p = wperm + off; off += (size_t)FOURH * EDIM;
    float* eWhh0p = wperm + off; off += (size_t)FOURH * HD;
    float* eWih1p = wperm + off; off += (size_t)FOURH * HD;
    float* eWhh1p = wperm + off; off += (size_t)FOURH * HD;
    float* dWih0p = wperm + off; off += (size_t)FOURH * EDIM;
    float* dWhh0p = wperm + off; off += (size_t)FOURH * HD;
    float* dWih1p = wperm + off; off += (size_t)FOURH * HD;
    float* dWhh1p = wperm + off; off += (size_t)FOURH * HD;

    // ---- setup ----
    {
        int nE = FOURH * EDIM, nH = FOURH * HD;
        permW_k<<<(nE + 255) / 256, 256>>>(eW_ih0, eWih0p, EDIM);
        permW_k<<<(nH + 255) / 256, 256>>>(eW_hh0, eWhh0p, HD);
        permW_k<<<(nH + 255) / 256, 256>>>(eW_ih1, eWih1p, HD);
        permW_k<<<(nH + 255) / 256, 256>>>(eW_hh1, eWhh1p, HD);
        permW_k<<<(nE + 255) / 256, 256>>>(dW_ih0, dWih0p, EDIM);
        permW_k<<<(nH + 255) / 256, 256>>>(dW_hh0, dWhh0p, HD);
        permW_k<<<(nH + 255) / 256, 256>>>(dW_ih1, dWih1p, HD);
        permW_k<<<(nH + 255) / 256, 256>>>(dW_hh1, dWhh1p, HD);
        permB_k<<<(4 * FOURH + 255) / 256, 256>>>(eb_ih0, eb_hh0, eb_ih1, eb_hh1,
                                                  db_ih0, db_hh0, db_ih1, db_hh1, bsum);
        embr_k<<<(VOCAB * EDIM + 255) / 256, 256>>>(emb, embr);
        int n4 = 6 * BATCH * HD / 4;
        zero_k<<<(n4 + 255) / 256, 256>>>(state, n4);
        build_dectok_k<<<(BATCH * SEQ + 255) / 256, 256>>>(tgt, dectok);
    }

    const dim3 gBig(FOURH / BN, MROWS / BM);   // (32, 384)
    const dim3 gRec(FOURH / BN, BATCH / BM);   // (32, 16)

    // ===== encoder layer 0 =====
    gemm_tf32<0><<<gBig, 256>>>(embr, src, eWih0p, bsum + 0 * FOURH, nullptr, Xg,
                                nullptr, nullptr, nullptr, 0, EDIM, 0);
    for (int t = 0; t < SEQ; ++t)
        gemm_tf32<1><<<gRec, 256>>>(h0buf[t & 1], nullptr, eWhh0p, nullptr, Xg, nullptr,
                                    h0buf[(t + 1) & 1], c0, y, 1, HD, t);
    // ===== encoder layer 1 =====
    gemm_tf32<0><<<gBig, 256>>>(y, nullptr, eWih1p, bsum + 1 * FOURH, nullptr, Xg,
                                nullptr, nullptr, nullptr, 0, HD, 0);
    for (int t = 0; t < SEQ; ++t)
        gemm_tf32<1><<<gRec, 256>>>(h1buf[t & 1], nullptr, eWhh1p, nullptr, Xg, nullptr,
                                    h1buf[(t + 1) & 1], c1, nullptr, 0, HD, t);
    // ===== decoder layer 0 (state continues: SEQ even -> final h back in buf[0]) =====
    gemm_tf32<0><<<gBig, 256>>>(embr, dectok, dWih0p, bsum + 2 * FOURH, nullptr, Xg,
                                nullptr, nullptr, nullptr, 0, EDIM, 0);
    for (int t = 0; t < SEQ; ++t)
        gemm_tf32<1><<<gRec, 256>>>(h0buf[t & 1], nullptr, dWhh0p, nullptr, Xg, nullptr,
                                    h0buf[(t + 1) & 1], c0, y, 1, HD, t);
    // ===== decoder layer 1 =====
    gemm_tf32<0><<<gBig, 256>>>(y, nullptr, dWih1p, bsum + 3 * FOURH, nullptr, Xg,
                                nullptr, nullptr, nullptr, 0, HD, 0);
    for (int t = 0; t < SEQ; ++t)
        gemm_tf32<1><<<gRec, 256>>>(h1buf[t & 1], nullptr, dWhh1p, nullptr, Xg, nullptr,
                                    h1buf[(t + 1) & 1], c1, y, 1, HD, t);
    // ===== output projection =====
    proj_k<<<MROWS / 128, 256>>>(y, fcW, fcb, out);
}

// round 10
// speedup vs baseline: 1.0107x; 1.0107x over previous
#include <cuda_runtime.h>
#include <cstdint>
#include <math.h>

// ---------------- problem constants ----------------
#define HD     1024
#define FOURH  4096
#define BATCH  2048
#define SEQ    24
#define EDIM   256
#define VOCAB  37
#define MROWS  (BATCH*SEQ)   // 49152

// ---------------- device scratch (no allocation allowed) ----------------
__device__ float g_Xg[(size_t)MROWS * FOURH];      // 805 MB : per-layer input projections (gate-interleaved cols)
__device__ float g_y[(size_t)MROWS * HD];          // 201 MB : per-layer outputs (tf32-rounded)
__device__ float g_state[(size_t)6 * BATCH * HD];  // h0a,h0b,c0,h1a,h1b,c1
__device__ float g_wperm[(size_t)2*4096*256 + (size_t)6*4096*1024]; // 109 MB permuted+rounded weights
__device__ float g_bsum[4 * FOURH];                // merged permuted biases per layer
__device__ float g_embr[VOCAB * EDIM];             // tf32-rounded embedding
__device__ int   g_dectok[BATCH * SEQ];

// ---------------- small helpers ----------------
__device__ __forceinline__ float tf32r(float x) {
    uint32_t r;
    asm("cvt.rna.tf32.f32 %0, %1;" : "=r"(r) : "f"(x));
    return __uint_as_float(r);
}

__device__ __forceinline__ void mma_tf32(float* c, const uint32_t* a, const uint32_t* b) {
    asm volatile(
        "mma.sync.aligned.m16n8k8.row.col.f32.tf32.tf32.f32 "
        "{%0,%1,%2,%3}, {%4,%5,%6,%7}, {%8,%9}, {%0,%1,%2,%3};\n"
        : "+f"(c[0]), "+f"(c[1]), "+f"(c[2]), "+f"(c[3])
        : "r"(a[0]), "r"(a[1]), "r"(a[2]), "r"(a[3]), "r"(b[0]), "r"(b[1]));
}

__device__ __forceinline__ void cp16(void* s, const void* g) {
    uint32_t sa = (uint32_t)__cvta_generic_to_shared(s);
    asm volatile("cp.async.ca.shared.global [%0], [%1], 16;\n" :: "r"(sa), "l"(g));
}
#define CP_COMMIT() asm volatile("cp.async.commit_group;\n" ::)
#define CP_WAIT(n)  asm volatile("cp.async.wait_group %0;\n" :: "n"(n))

__device__ __forceinline__ float sigf(float x) { return 1.f / (1.f + expf(-x)); }

// ---------------- GEMM: C[M,4096] = A[M,K] @ Wp[4096,K]^T (+ fused epilogue) ----------------
// Weights are gate-interleaved: permuted row r' = 4u+g (orig row g*1024+u) -> output columns
// come as [i f g o] per hidden unit. All MMA operands are pre-rounded to tf32.
// MODE 0: input projection.  A row m = (tok ? embr[tok[m]] : A[m]).  C = acc + bsum.
// MODE 1: recurrent step + fused LSTM cell.  A = h_read.  gates = acc + Xg[(m*SEQ+t)*4096+col];
//         c updated in-place; new h written to ping-pong buffer hW (never the read buffer ->
//         no cross-block read/write race) and optionally y[m*SEQ+t].
// Pipeline: 4-stage cp.async, ONE __syncthreads per k-iter (cutlass-style), empty commits at tail.
constexpr int BM = 128, BN = 128, BK = 16, SPAD = 4;  // smem stride 20 -> conflict-free scalar LDS
constexpr int STAGES = 4;
constexpr int SMEM_BYTES = STAGES * (BM + BN) * (BK + SPAD) * 4;  // 81920

template<int MODE>
__global__ __launch_bounds__(128)
void gemm_tf32(const float* __restrict__ A, const int* __restrict__ tok,
               const float* __restrict__ W,
               const float* __restrict__ bsum,
               const float* __restrict__ Xg,
               float* __restrict__ C,          // MODE0: Xg out
               float* __restrict__ hW, float* __restrict__ cP,  // MODE1
               float* __restrict__ yP, int writeY,
               int K, int t)
{
    extern __shared__ float smem[];
    float (*sA)[BM][BK + SPAD] = (float (*)[BM][BK + SPAD])smem;
    float (*sB)[BN][BK + SPAD] = (float (*)[BN][BK + SPAD])(smem + STAGES * BM * (BK + SPAD));

    const int tid  = threadIdx.x;
    const int bm   = blockIdx.y * BM;
    const int bn   = blockIdx.x * BN;
    const int ldr  = tid >> 2;          // 0..31
    const int ldc  = (tid & 3) * 4;     // 0,4,8,12

    // loader base pointers (token gather folded in)
    const float* abase[4];
    const float* bbase[4];
#pragma unroll
    for (int i = 0; i < 4; ++i) {
        int m = bm + ldr + i * 32;
        const float* base = tok ? (A + (size_t)tok[m] * K) : (A + (size_t)m * K);
        abase[i] = base + ldc;
        bbase[i] = W + (size_t)(bn + ldr + i * 32) * K + ldc;
    }

    const int KT = K / BK;

    // prologue: stage 0..STAGES-2 (3 groups in flight)
#pragma unroll
    for (int s = 0; s < STAGES - 1; ++s) {
        if (s < KT) {
#pragma unroll
            for (int i = 0; i < 4; ++i) cp16(&sA[s][ldr + i * 32][ldc], abase[i] + s * BK);
#pragma unroll
            for (int i = 0; i < 4; ++i) cp16(&sB[s][ldr + i * 32][ldc], bbase[i] + s * BK);
        }
        CP_COMMIT();
    }

    const int wid  = tid >> 5;
    const int lane = tid & 31;
    const int wm   = (wid >> 1) * 64;   // warp M offset
    const int wn   = (wid & 1) * 64;    // warp N offset
    const int lr   = lane >> 2;         // 0..7
    const int lc   = lane & 3;          // 0..3

    float acc[4][8][4];
#pragma unroll
    for (int a = 0; a < 4; ++a)
#pragma unroll
        for (int b = 0; b < 8; ++b)
#pragma unroll
            for (int q = 0; q < 4; ++q) acc[a][b][q] = 0.f;

    for (int kt = 0; kt < KT; ++kt) {
        CP_WAIT(STAGES - 2);             // tile kt's group complete (per-thread)
        __syncthreads();                 // -> ALL threads' tile-kt data landed; prev compute done
        const int buf = kt & (STAGES - 1);
#pragma unroll
        for (int ks = 0; ks < 2; ++ks) {
            const int k0 = ks * 8;
            uint32_t af[4][4], bf[8][2];
#pragma unroll
            for (int mt = 0; mt < 4; ++mt) {
                int r = wm + mt * 16 + lr;
                af[mt][0] = __float_as_uint(sA[buf][r][k0 + lc]);
                af[mt][1] = __float_as_uint(sA[buf][r + 8][k0 + lc]);
                af[mt][2] = __float_as_uint(sA[buf][r][k0 + lc + 4]);
                af[mt][3] = __float_as_uint(sA[buf][r + 8][k0 + lc + 4]);
            }
#pragma unroll
            for (int nt = 0; nt < 8; ++nt) {
                int n = wn + nt * 8 + lr;
                bf[nt][0] = __float_as_uint(sB[buf][n][k0 + lc]);
                bf[nt][1] = __float_as_uint(sB[buf][n][k0 + lc + 4]);
            }
#pragma unroll
            for (int mt = 0; mt < 4; ++mt)
#pragma unroll
                for (int nt = 0; nt < 8; ++nt)
                    mma_tf32(acc[mt][nt], af[mt], bf[nt]);
        }
        // prefetch tile kt+STAGES-1 into slot (kt-1)%STAGES (freed: computed last iter,
        // and all warps passed this iter's barrier). Always commit to keep group counts exact.
        const int pt = kt + STAGES - 1;
        if (pt < KT) {
            const int ps = pt & (STAGES - 1);
#pragma unroll
            for (int i = 0; i < 4; ++i) cp16(&sA[ps][ldr + i * 32][ldc], abase[i] + pt * BK);
#pragma unroll
            for (int i = 0; i < 4; ++i) cp16(&sB[ps][ldr + i * 32][ldc], bbase[i] + pt * BK);
        }
        CP_COMMIT();
    }

    // ---------------- epilogue ----------------
#pragma unroll
    for (int mt = 0; mt < 4; ++mt) {
        const int gr0 = bm + wm + mt * 16 + lr;
        const int gr1 = gr0 + 8;
#pragma unroll
        for (int nt = 0; nt < 8; ++nt) {
            const int gc = bn + wn + nt * 8 + lc * 2;
            if (MODE == 0) {
                float bx = bsum[gc], by = bsum[gc + 1];
                float2 v0, v1;
                v0.x = acc[mt][nt][0] + bx; v0.y = acc[mt][nt][1] + by;
                v1.x = acc[mt][nt][2] + bx; v1.y = acc[mt][nt][3] + by;
                *(float2*)&C[(size_t)gr0 * FOURH + gc] = v0;
                *(float2*)&C[(size_t)gr1 * FOURH + gc] = v1;
            } else {
                // gates = acc + Xg ; columns interleaved: even lc*2 -> (i,f), odd -> (g,o)
                float2 x0 = *(const float2*)&Xg[((size_t)gr0 * SEQ + t) * FOURH + gc];
                float2 x1 = *(const float2*)&Xg[((size_t)gr1 * SEQ + t) * FOURH + gc];
                float v0 = acc[mt][nt][0] + x0.x;
                float v1 = acc[mt][nt][1] + x0.y;
                float v2 = acc[mt][nt][2] + x1.x;
                float v3 = acc[mt][nt][3] + x1.y;
                float p0 = __shfl_xor_sync(0xffffffffu, v0, 1);
                float p1 = __shfl_xor_sync(0xffffffffu, v1, 1);
                float p2 = __shfl_xor_sync(0xffffffffu, v2, 1);
                float p3 = __shfl_xor_sync(0xffffffffu, v3, 1);
                if ((lane & 1) == 0) {
                    // this lane holds (i,f); partner supplied (g,o)
                    const int u = gc >> 2;
                    const size_t cb0 = (size_t)gr0 * HD + u;
                    const size_t cb1 = (size_t)gr1 * HD + u;
                    float c0 = cP[cb0], c1 = cP[cb1];
                    c0 = sigf(v1) * c0 + sigf(v0) * tanhf(p0);
                    c1 = sigf(v3) * c1 + sigf(v2) * tanhf(p2);
                    float h0 = sigf(p1) * tanhf(c0);
                    float h1 = sigf(p3) * tanhf(c1);
                    cP[cb0] = c0; cP[cb1] = c1;
                    h0 = tf32r(h0); h1 = tf32r(h1);
                    hW[cb0] = h0; hW[cb1] = h1;
                    if (writeY) {
                        yP[((size_t)gr0 * SEQ + t) * HD + u] = h0;
                        yP[((size_t)gr1 * SEQ + t) * HD + u] = h1;
                    }
                }
            }
        }
    }
}

// ---------------- setup kernels ----------------
// permute rows g*1024+u -> 4u+g, round to tf32
__global__ void permW_k(const float* __restrict__ in, float* __restrict__ out, int K)
{
    int idx = blockIdx.x * blockDim.x + threadIdx.x;
    if (idx < FOURH * K) {
        int rp = idx / K, k = idx - rp * K;
        int orig = (rp & 3) * HD + (rp >> 2);
        out[idx] = tf32r(in[orig * K + k]);
    }
}

__global__ void permB_k(const float* bi0, const float* bh0, const float* bi1, const float* bh1,
                        const float* bi2, const float* bh2, const float* bi3, const float* bh3,
                        float* __restrict__ out)
{
    int idx = blockIdx.x * blockDim.x + threadIdx.x;   // over 4*4096
    if (idx < 4 * FOURH) {
        int l = idx >> 12, rp = idx & (FOURH - 1);
        int orig = (rp & 3) * HD + (rp >> 2);
        const float* bi = (l == 0) ? bi0 : (l == 1) ? bi1 : (l == 2) ? bi2 : bi3;
        const float* bh = (l == 0) ? bh0 : (l == 1) ? bh1 : (l == 2) ? bh2 : bh3;
        out[idx] = bi[orig] + bh[orig];
    }
}

__global__ void embr_k(const float* __restrict__ emb, float* __restrict__ out)
{
    int i = blockIdx.x * blockDim.x + threadIdx.x;
    if (i < VOCAB * EDIM) out[i] = tf32r(emb[i]);
}

__global__ void zero_k(float* p, int n4)
{
    int i = blockIdx.x * blockDim.x + threadIdx.x;
    if (i < n4) ((float4*)p)[i] = make_float4(0.f, 0.f, 0.f, 0.f);
}

__global__ void build_dectok_k(const int* __restrict__ tgt, int* __restrict__ dt)
{
    int idx = blockIdx.x * blockDim.x + threadIdx.x;
    if (idx < BATCH * SEQ) {
        int b = idx / SEQ, t = idx - b * SEQ;
        dt[idx] = (t == 0) ? 1 : tgt[b * SEQ + t - 1];
    }
}

// ---------------- output projection: out[M,37] = y[M,1024] @ fcW[37,1024]^T + fcb ----------------
__global__ __launch_bounds__(256)
void proj_k(const float* __restrict__ y, const float* __restrict__ fcW,
            const float* __restrict__ fcb, float* __restrict__ out)
{
    __shared__ float ys[128][65];
    __shared__ float ws[40][65];
    const int tid = threadIdx.x;
    const int gm0 = blockIdx.x * 128;
    const int r0  = (tid >> 3) * 4;
    const int n0  = (tid & 7) * 5;

    float acc[4][5];
#pragma unroll
    for (int i = 0; i < 4; ++i)
#pragma unroll
        for (int j = 0; j < 5; ++j) acc[i][j] = 0.f;

    for (int kc = 0; kc < 16; ++kc) {
        __syncthreads();
        for (int i = tid; i < 128 * 16; i += 256) {
            int r = i >> 4, c4 = (i & 15) * 4;
            float4 v = *(const float4*)&y[(size_t)(gm0 + r) * HD + kc * 64 + c4];
            ys[r][c4] = v.x; ys[r][c4 + 1] = v.y; ys[r][c4 + 2] = v.z; ys[r][c4 + 3] = v.w;
        }
        for (int i = tid; i < 40 * 64; i += 256) {
            int n = i >> 6, cc = i & 63;
            ws[n][cc] = (n < VOCAB) ? fcW[n * HD + kc * 64 + cc] : 0.f;
        }
        __syncthreads();
#pragma unroll 8
        for (int k = 0; k < 64; ++k) {
            float yv[4], wv[5];
#pragma unroll
            for (int i = 0; i < 4; ++i) yv[i] = ys[r0 + i][k];
#pragma unroll
            for (int j = 0; j < 5; ++j) wv[j] = ws[n0 + j][k];
#pragma unroll
            for (int i = 0; i < 4; ++i)
#pragma unroll
                for (int j = 0; j < 5; ++j) acc[i][j] += yv[i] * wv[j];
        }
    }
#pragma unroll
    for (int i = 0; i < 4; ++i)
#pragma unroll
        for (int j = 0; j < 5; ++j) {
            int n = n0 + j;
            if (n < VOCAB)
                out[(size_t)(gm0 + r0 + i) * VOCAB + n] = acc[i][j] + fcb[n];
        }
}

// ---------------- host driver ----------------
extern "C" void kernel_launch(void* const* d_in, const int* in_sizes, int n_in,
                              void* d_out, int out_size)
{
    const int*   src    = (const int*)d_in[0];
    const int*   tgt    = (const int*)d_in[1];
    const float* emb    = (const float*)d_in[2];
    const float* eW_ih0 = (const float*)d_in[3];
    const float* eW_hh0 = (const float*)d_in[4];
    const float* eb_ih0 = (const float*)d_in[5];
    const float* eb_hh0 = (const float*)d_in[6];
    const float* eW_ih1 = (const float*)d_in[7];
    const float* eW_hh1 = (const float*)d_in[8];
    const float* eb_ih1 = (const float*)d_in[9];
    const float* eb_hh1 = (const float*)d_in[10];
    const float* dW_ih0 = (const float*)d_in[11];
    const float* dW_hh0 = (const float*)d_in[12];
    const float* db_ih0 = (const float*)d_in[13];
    const float* db_hh0 = (const float*)d_in[14];
    const float* dW_ih1 = (const float*)d_in[15];
    const float* dW_hh1 = (const float*)d_in[16];
    const float* db_ih1 = (const float*)d_in[17];
    const float* db_hh1 = (const float*)d_in[18];
    const float* fcW    = (const float*)d_in[19];
    const float* fcb    = (const float*)d_in[20];
    float* out = (float*)d_out;

    float *Xg, *y, *state, *wperm, *bsum, *embr;
    int*   dectok;
    cudaGetSymbolAddress((void**)&Xg,     g_Xg);
    cudaGetSymbolAddress((void**)&y,      g_y);
    cudaGetSymbolAddress((void**)&state,  g_state);
    cudaGetSymbolAddress((void**)&wperm,  g_wperm);
    cudaGetSymbolAddress((void**)&bsum,   g_bsum);
    cudaGetSymbolAddress((void**)&embr,   g_embr);
    cudaGetSymbolAddress((void**)&dectok, g_dectok);

    // allow 82 KB dynamic smem on both GEMM instantiations (idempotent)
    cudaFuncSetAttribute(gemm_tf32<0>, cudaFuncAttributeMaxDynamicSharedMemorySize, SMEM_BYTES);
    cudaFuncSetAttribute(gemm_tf32<1>, cudaFuncAttributeMaxDynamicSharedMemorySize, SMEM_BYTES);

    // h ping-pong buffers + c per layer chain
    float* h0buf[2] = { state,
                        state + (size_t)1 * BATCH * HD };
    float* c0      =   state + (size_t)2 * BATCH * HD;
    float* h1buf[2] = { state + (size_t)3 * BATCH * HD,
                        state + (size_t)4 * BATCH * HD };
    float* c1      =   state + (size_t)5 * BATCH * HD;

    // permuted weight layout inside g_wperm
    size_t off = 0;
    float* eWih0p = wperm + off; off += (size_t)FOURH * EDIM;
    float* eWhh0p = wperm + off; off += (size_t)FOURH * HD;
    float* eWih1p = wperm + off; off += (size_t)FOURH * HD;
    float* eWhh1p = wperm + off; off += (size_t)FOURH * HD;
    float* dWih0p = wperm + off; off += (size_t)FOURH * EDIM;
    float* dWhh0p = wperm + off; off += (size_t)FOURH * HD;
    float* dWih1p = wperm + off; off += (size_t)FOURH * HD;
    float* dWhh1p = wperm + off; off += (size_t)FOURH * HD;

    // ---- setup ----
    {
        int nE = FOURH * EDIM, nH = FOURH * HD;
        permW_k<<<(nE + 255) / 256, 256>>>(eW_ih0, eWih0p, EDIM);
        permW_k<<<(nH + 255) / 256, 256>>>(eW_hh0, eWhh0p, HD);
        permW_k<<<(nH + 255) / 256, 256>>>(eW_ih1, eWih1p, HD);
        permW_k<<<(nH + 255) / 256, 256>>>(eW_hh1, eWhh1p, HD);
        permW_k<<<(nE + 255) / 256, 256>>>(dW_ih0, dWih0p, EDIM);
        permW_k<<<(nH + 255) / 256, 256>>>(dW_hh0, dWhh0p, HD);
        permW_k<<<(nH + 255) / 256, 256>>>(dW_ih1, dWih1p, HD);
        permW_k<<<(nH + 255) / 256, 256>>>(dW_hh1, dWhh1p, HD);
        permB_k<<<(4 * FOURH + 255) / 256, 256>>>(eb_ih0, eb_hh0, eb_ih1, eb_hh1,
                                                  db_ih0, db_hh0, db_ih1, db_hh1, bsum);
        embr_k<<<(VOCAB * EDIM + 255) / 256, 256>>>(emb, embr);
        int n4 = 6 * BATCH * HD / 4;
        zero_k<<<(n4 + 255) / 256, 256>>>(state, n4);
        build_dectok_k<<<(BATCH * SEQ + 255) / 256, 256>>>(tgt, dectok);
    }

    const dim3 gBig(FOURH / BN, MROWS / BM);   // (32, 384)
    const dim3 gRec(FOURH / BN, BATCH / BM);   // (32, 16)

    // ===== encoder layer 0 =====
    gemm_tf32<0><<<gBig, 128, SMEM_BYTES>>>(embr, src, eWih0p, bsum + 0 * FOURH, nullptr, Xg,
                                            nullptr, nullptr, nullptr, 0, EDIM, 0);
    for (int t = 0; t < SEQ; ++t)
        gemm_tf32<1><<<gRec, 128, SMEM_BYTES>>>(h0buf[t & 1], nullptr, eWhh0p, nullptr, Xg, nullptr,
                                                h0buf[(t + 1) & 1], c0, y, 1, HD, t);
    // ===== encoder layer 1 =====
    gemm_tf32<0><<<gBig, 128, SMEM_BYTES>>>(y, nullptr, eWih1p, bsum + 1 * FOURH, nullptr, Xg,
                                            nullptr, nullptr, nullptr, 0, HD, 0);
    for (int t = 0; t < SEQ; ++t)
        gemm_tf32<1><<<gRec, 128, SMEM_BYTES>>>(h1buf[t & 1], nullptr, eWhh1p, nullptr, Xg, nullptr,
                                                h1buf[(t + 1) & 1], c1, nullptr, 0, HD, t);
    // ===== decoder layer 0 (SEQ even -> encoder-final h is back in buf[0]) =====
    gemm_tf32<0><<<gBig, 128, SMEM_BYTES>>>(embr, dectok, dWih0p, bsum + 2 * FOURH, nullptr, Xg,
                                            nullptr, nullptr, nullptr, 0, EDIM, 0);
    for (int t = 0; t < SEQ; ++t)
        gemm_tf32<1><<<gRec, 128, SMEM_BYTES>>>(h0buf[t & 1], nullptr, dWhh0p, nullptr, Xg, nullptr,
                                                h0buf[(t + 1) & 1], c0, y, 1, HD, t);
    // ===== decoder layer 1 =====
    gemm_tf32<0><<<gBig, 128, SMEM_BYTES>>>(y, nullptr, dWih1p, bsum + 3 * FOURH, nullptr, Xg,
                                            nullptr, nullptr, nullptr, 0, HD, 0);
    for (int t = 0; t < SEQ; ++t)
        gemm_tf32<1><<<gRec, 128, SMEM_BYTES>>>(h1buf[t & 1], nullptr, dWhh1p, nullptr, Xg, nullptr,
                                                h1buf[(t + 1) & 1], c1, y, 1, HD, t);
    // ===== output projection =====
    proj_k<<<MROWS / 128, 256>>>(y, fcW, fcb, out);
}

// round 11
// speedup vs baseline: 1.0141x; 1.0033x over previous
#include <cuda_runtime.h>
#include <cstdint>
#include <math.h>

// ---------------- problem constants ----------------
#define HD     1024
#define FOURH  4096
#define BATCH  2048
#define SEQ    24
#define EDIM   256
#define VOCAB  37
#define MROWS  (BATCH*SEQ)   // 49152

// ---------------- device scratch (no allocation allowed) ----------------
__device__ float g_Xg[(size_t)MROWS * FOURH];      // 805 MB : per-layer input projections (gate-interleaved cols)
__device__ float g_y[(size_t)MROWS * HD];          // 201 MB : per-layer outputs (tf32-rounded)
__device__ float g_state[(size_t)6 * BATCH * HD];  // h0a,h0b,c0,h1a,h1b,c1
__device__ float g_wperm[(size_t)2*4096*256 + (size_t)6*4096*1024]; // 109 MB permuted+rounded weights
__device__ float g_bsum[4 * FOURH];                // merged permuted biases per layer
__device__ float g_embr[VOCAB * EDIM];             // tf32-rounded embedding
__device__ int   g_dectok[BATCH * SEQ];

// ---------------- small helpers ----------------
__device__ __forceinline__ float tf32r(float x) {
    uint32_t r;
    asm("cvt.rna.tf32.f32 %0, %1;" : "=r"(r) : "f"(x));
    return __uint_as_float(r);
}

__device__ __forceinline__ void mma_tf32(float* c, const uint32_t* a, const uint32_t* b) {
    asm volatile(
        "mma.sync.aligned.m16n8k8.row.col.f32.tf32.tf32.f32 "
        "{%0,%1,%2,%3}, {%4,%5,%6,%7}, {%8,%9}, {%0,%1,%2,%3};\n"
        : "+f"(c[0]), "+f"(c[1]), "+f"(c[2]), "+f"(c[3])
        : "r"(a[0]), "r"(a[1]), "r"(a[2]), "r"(a[3]), "r"(b[0]), "r"(b[1]));
}

__device__ __forceinline__ void cp16(void* s, const void* g) {
    uint32_t sa = (uint32_t)__cvta_generic_to_shared(s);
    asm volatile("cp.async.ca.shared.global [%0], [%1], 16;\n" :: "r"(sa), "l"(g));
}
#define CP_COMMIT() asm volatile("cp.async.commit_group;\n" ::)
#define CP_WAIT(n)  asm volatile("cp.async.wait_group %0;\n" :: "n"(n))

__device__ __forceinline__ float sigf(float x) { return 1.f / (1.f + expf(-x)); }

// ---------------- GEMM: C[M,4096] = A[M,K] @ Wp[4096,K]^T (+ fused epilogue) ----------------
// Weights are gate-interleaved: permuted row r' = 4u+g (orig row g*1024+u) -> output columns
// come as [i f g o] per hidden unit. All MMA operands are pre-rounded to tf32.
// MODE 0: input projection.  A row m = (tok ? embr[tok[m]] : A[m]).  C = acc + bsum.
// MODE 1: recurrent step + fused LSTM cell.  A = h_read.  gates = acc + Xg[(m*SEQ+t)*4096+col];
//         c updated in-place; new h written to ping-pong buffer hW (never the read buffer ->
//         no cross-block read/write race) and optionally y[m*SEQ+t].
// Pipeline: 4-stage cp.async, ONE __syncthreads per k-iter (cutlass-style), empty commits at tail.
constexpr int BM = 128, BN = 128, BK = 16, SPAD = 4;  // smem stride 20 -> conflict-free scalar LDS
constexpr int STAGES = 4;
constexpr int SMEM_BYTES = STAGES * (BM + BN) * (BK + SPAD) * 4;  // 81920

template<int MODE>
__global__ __launch_bounds__(128)
void gemm_tf32(const float* __restrict__ A, const int* __restrict__ tok,
               const float* __restrict__ W,
               const float* __restrict__ bsum,
               const float* __restrict__ Xg,
               float* __restrict__ C,          // MODE0: Xg out
               float* __restrict__ hW, float* __restrict__ cP,  // MODE1
               float* __restrict__ yP, int writeY,
               int K, int t)
{
    extern __shared__ float smem[];
    float (*sA)[BM][BK + SPAD] = (float (*)[BM][BK + SPAD])smem;
    float (*sB)[BN][BK + SPAD] = (float (*)[BN][BK + SPAD])(smem + STAGES * BM * (BK + SPAD));

    const int tid  = threadIdx.x;
    const int bm   = blockIdx.y * BM;
    const int bn   = blockIdx.x * BN;
    const int ldr  = tid >> 2;          // 0..31
    const int ldc  = (tid & 3) * 4;     // 0,4,8,12

    // loader base pointers (token gather folded in)
    const float* abase[4];
    const float* bbase[4];
#pragma unroll
    for (int i = 0; i < 4; ++i) {
        int m = bm + ldr + i * 32;
        const float* base = tok ? (A + (size_t)tok[m] * K) : (A + (size_t)m * K);
        abase[i] = base + ldc;
        bbase[i] = W + (size_t)(bn + ldr + i * 32) * K + ldc;
    }

    const int KT = K / BK;

    // prologue: stage 0..STAGES-2 (3 groups in flight)
#pragma unroll
    for (int s = 0; s < STAGES - 1; ++s) {
        if (s < KT) {
#pragma unroll
            for (int i = 0; i < 4; ++i) cp16(&sA[s][ldr + i * 32][ldc], abase[i] + s * BK);
#pragma unroll
            for (int i = 0; i < 4; ++i) cp16(&sB[s][ldr + i * 32][ldc], bbase[i] + s * BK);
        }
        CP_COMMIT();
    }

    const int wid  = tid >> 5;
    const int lane = tid & 31;
    const int wm   = (wid >> 1) * 64;   // warp M offset
    const int wn   = (wid & 1) * 64;    // warp N offset
    const int lr   = lane >> 2;         // 0..7
    const int lc   = lane & 3;          // 0..3

    float acc[4][8][4];
#pragma unroll
    for (int a = 0; a < 4; ++a)
#pragma unroll
        for (int b = 0; b < 8; ++b)
#pragma unroll
            for (int q = 0; q < 4; ++q) acc[a][b][q] = 0.f;

    for (int kt = 0; kt < KT; ++kt) {
        CP_WAIT(STAGES - 2);             // tile kt's group complete (per-thread)
        __syncthreads();                 // -> ALL threads' tile-kt data landed; prev compute done
        const int buf = kt & (STAGES - 1);
#pragma unroll
        for (int ks = 0; ks < 2; ++ks) {
            const int k0 = ks * 8;
            uint32_t af[4][4], bf[8][2];
#pragma unroll
            for (int mt = 0; mt < 4; ++mt) {
                int r = wm + mt * 16 + lr;
                af[mt][0] = __float_as_uint(sA[buf][r][k0 + lc]);
                af[mt][1] = __float_as_uint(sA[buf][r + 8][k0 + lc]);
                af[mt][2] = __float_as_uint(sA[buf][r][k0 + lc + 4]);
                af[mt][3] = __float_as_uint(sA[buf][r + 8][k0 + lc + 4]);
            }
#pragma unroll
            for (int nt = 0; nt < 8; ++nt) {
                int n = wn + nt * 8 + lr;
                bf[nt][0] = __float_as_uint(sB[buf][n][k0 + lc]);
                bf[nt][1] = __float_as_uint(sB[buf][n][k0 + lc + 4]);
            }
#pragma unroll
            for (int mt = 0; mt < 4; ++mt)
#pragma unroll
                for (int nt = 0; nt < 8; ++nt)
                    mma_tf32(acc[mt][nt], af[mt], bf[nt]);
        }
        // prefetch tile kt+STAGES-1 into slot (kt-1)%STAGES (freed: computed last iter,
        // and all warps passed this iter's barrier). Always commit to keep group counts exact.
        const int pt = kt + STAGES - 1;
        if (pt < KT) {
            const int ps = pt & (STAGES - 1);
#pragma unroll
            for (int i = 0; i < 4; ++i) cp16(&sA[ps][ldr + i * 32][ldc], abase[i] + pt * BK);
#pragma unroll
            for (int i = 0; i < 4; ++i) cp16(&sB[ps][ldr + i * 32][ldc], bbase[i] + pt * BK);
        }
        CP_COMMIT();
    }

    // ---------------- epilogue ----------------
#pragma unroll
    for (int mt = 0; mt < 4; ++mt) {
        const int gr0 = bm + wm + mt * 16 + lr;
        const int gr1 = gr0 + 8;
#pragma unroll
        for (int nt = 0; nt < 8; ++nt) {
            const int gc = bn + wn + nt * 8 + lc * 2;
            if (MODE == 0) {
                float bx = bsum[gc], by = bsum[gc + 1];
                float2 v0, v1;
                v0.x = acc[mt][nt][0] + bx; v0.y = acc[mt][nt][1] + by;
                v1.x = acc[mt][nt][2] + bx; v1.y = acc[mt][nt][3] + by;
                *(float2*)&C[(size_t)gr0 * FOURH + gc] = v0;
                *(float2*)&C[(size_t)gr1 * FOURH + gc] = v1;
            } else {
                // gates = acc + Xg ; columns interleaved: even lc*2 -> (i,f), odd -> (g,o)
                float2 x0 = *(const float2*)&Xg[((size_t)gr0 * SEQ + t) * FOURH + gc];
                float2 x1 = *(const float2*)&Xg[((size_t)gr1 * SEQ + t) * FOURH + gc];
                float v0 = acc[mt][nt][0] + x0.x;
                float v1 = acc[mt][nt][1] + x0.y;
                float v2 = acc[mt][nt][2] + x1.x;
                float v3 = acc[mt][nt][3] + x1.y;
                float p0 = __shfl_xor_sync(0xffffffffu, v0, 1);
                float p1 = __shfl_xor_sync(0xffffffffu, v1, 1);
                float p2 = __shfl_xor_sync(0xffffffffu, v2, 1);
                float p3 = __shfl_xor_sync(0xffffffffu, v3, 1);
                if ((lane & 1) == 0) {
                    // this lane holds (i,f); partner supplied (g,o)
                    const int u = gc >> 2;
                    const size_t cb0 = (size_t)gr0 * HD + u;
                    const size_t cb1 = (size_t)gr1 * HD + u;
                    float c0 = cP[cb0], c1 = cP[cb1];
                    c0 = sigf(v1) * c0 + sigf(v0) * tanhf(p0);
                    c1 = sigf(v3) * c1 + sigf(v2) * tanhf(p2);
                    float h0 = sigf(p1) * tanhf(c0);
                    float h1 = sigf(p3) * tanhf(c1);
                    cP[cb0] = c0; cP[cb1] = c1;
                    h0 = tf32r(h0); h1 = tf32r(h1);
                    hW[cb0] = h0; hW[cb1] = h1;
                    if (writeY) {
                        yP[((size_t)gr0 * SEQ + t) * HD + u] = h0;
                        yP[((size_t)gr1 * SEQ + t) * HD + u] = h1;
                    }
                }
            }
        }
    }
}

// ---------------- setup kernels ----------------
// permute rows g*1024+u -> 4u+g, round to tf32
__global__ void permW_k(const float* __restrict__ in, float* __restrict__ out, int K)
{
    int idx = blockIdx.x * blockDim.x + threadIdx.x;
    if (idx < FOURH * K) {
        int rp = idx / K, k = idx - rp * K;
        int orig = (rp & 3) * HD + (rp >> 2);
        out[idx] = tf32r(in[orig * K + k]);
    }
}

__global__ void permB_k(const float* bi0, const float* bh0, const float* bi1, const float* bh1,
                        const float* bi2, const float* bh2, const float* bi3, const float* bh3,
                        float* __restrict__ out)
{
    int idx = blockIdx.x * blockDim.x + threadIdx.x;   // over 4*4096
    if (idx < 4 * FOURH) {
        int l = idx >> 12, rp = idx & (FOURH - 1);
        int orig = (rp & 3) * HD + (rp >> 2);
        const float* bi = (l == 0) ? bi0 : (l == 1) ? bi1 : (l == 2) ? bi2 : bi3;
        const float* bh = (l == 0) ? bh0 : (l == 1) ? bh1 : (l == 2) ? bh2 : bh3;
        out[idx] = bi[orig] + bh[orig];
    }
}

__global__ void embr_k(const float* __restrict__ emb, float* __restrict__ out)
{
    int i = blockIdx.x * blockDim.x + threadIdx.x;
    if (i < VOCAB * EDIM) out[i] = tf32r(emb[i]);
}

__global__ void zero_k(float* p, int n4)
{
    int i = blockIdx.x * blockDim.x + threadIdx.x;
    if (i < n4) ((float4*)p)[i] = make_float4(0.f, 0.f, 0.f, 0.f);
}

__global__ void build_dectok_k(const int* __restrict__ tgt, int* __restrict__ dt)
{
    int idx = blockIdx.x * blockDim.x + threadIdx.x;
    if (idx < BATCH * SEQ) {
        int b = idx / SEQ, t = idx - b * SEQ;
        dt[idx] = (t == 0) ? 1 : tgt[b * SEQ + t - 1];
    }
}

// ---------------- output projection: out[M,37] = y[M,1024] @ fcW[37,1024]^T + fcb ----------------
__global__ __launch_bounds__(256)
void proj_k(const float* __restrict__ y, const float* __restrict__ fcW,
            const float* __restrict__ fcb, float* __restrict__ out)
{
    __shared__ float ys[128][65];
    __shared__ float ws[40][65];
    const int tid = threadIdx.x;
    const int gm0 = blockIdx.x * 128;
    const int r0  = (tid >> 3) * 4;
    const int n0  = (tid & 7) * 5;

    float acc[4][5];
#pragma unroll
    for (int i = 0; i < 4; ++i)
#pragma unroll
        for (int j = 0; j < 5; ++j) acc[i][j] = 0.f;

    for (int kc = 0; kc < 16; ++kc) {
        __syncthreads();
        for (int i = tid; i < 128 * 16; i += 256) {
            int r = i >> 4, c4 = (i & 15) * 4;
            float4 v = *(const float4*)&y[(size_t)(gm0 + r) * HD + kc * 64 + c4];
            ys[r][c4] = v.x; ys[r][c4 + 1] = v.y; ys[r][c4 + 2] = v.z; ys[r][c4 + 3] = v.w;
        }
        for (int i = tid; i < 40 * 64; i += 256) {
            int n = i >> 6, cc = i & 63;
            ws[n][cc] = (n < VOCAB) ? fcW[n * HD + kc * 64 + cc] : 0.f;
        }
        __syncthreads();
#pragma unroll 8
        for (int k = 0; k < 64; ++k) {
            float yv[4], wv[5];
#pragma unroll
            for (int i = 0; i < 4; ++i) yv[i] = ys[r0 + i][k];
#pragma unroll
            for (int j = 0; j < 5; ++j) wv[j] = ws[n0 + j][k];
#pragma unroll
            for (int i = 0; i < 4; ++i)
#pragma unroll
                for (int j = 0; j < 5; ++j) acc[i][j] += yv[i] * wv[j];
        }
    }
#pragma unroll
    for (int i = 0; i < 4; ++i)
#pragma unroll
        for (int j = 0; j < 5; ++j) {
            int n = n0 + j;
            if (n < VOCAB)
                out[(size_t)(gm0 + r0 + i) * VOCAB + n] = acc[i][j] + fcb[n];
        }
}

// ---------------- host driver ----------------
extern "C" void kernel_launch(void* const* d_in, const int* in_sizes, int n_in,
                              void* d_out, int out_size)
{
    const int*   src    = (const int*)d_in[0];
    const int*   tgt    = (const int*)d_in[1];
    const float* emb    = (const float*)d_in[2];
    const float* eW_ih0 = (const float*)d_in[3];
    const float* eW_hh0 = (const float*)d_in[4];
    const float* eb_ih0 = (const float*)d_in[5];
    const float* eb_hh0 = (const float*)d_in[6];
    const float* eW_ih1 = (const float*)d_in[7];
    const float* eW_hh1 = (const float*)d_in[8];
    const float* eb_ih1 = (const float*)d_in[9];
    const float* eb_hh1 = (const float*)d_in[10];
    const float* dW_ih0 = (const float*)d_in[11];
    const float* dW_hh0 = (const float*)d_in[12];
    const float* db_ih0 = (const float*)d_in[13];
    const float* db_hh0 = (const float*)d_in[14];
    const float* dW_ih1 = (const float*)d_in[15];
    const float* dW_hh1 = (const float*)d_in[16];
    const float* db_ih1 = (const float*)d_in[17];
    const float* db_hh1 = (const float*)d_in[18];
    const float* fcW    = (const float*)d_in[19];
    const float* fcb    = (const float*)d_in[20];
    float* out = (float*)d_out;

    float *Xg, *y, *state, *wperm, *bsum, *embr;
    int*   dectok;
    cudaGetSymbolAddress((void**)&Xg,     g_Xg);
    cudaGetSymbolAddress((void**)&y,      g_y);
    cudaGetSymbolAddress((void**)&state,  g_state);
    cudaGetSymbolAddress((void**)&wperm,  g_wperm);
    cudaGetSymbolAddress((void**)&bsum,   g_bsum);
    cudaGetSymbolAddress((void**)&embr,   g_embr);
    cudaGetSymbolAddress((void**)&dectok, g_dectok);

    // allow 82 KB dynamic smem on both GEMM instantiations (idempotent)
    cudaFuncSetAttribute(gemm_tf32<0>, cudaFuncAttributeMaxDynamicSharedMemorySize, SMEM_BYTES);
    cudaFuncSetAttribute(gemm_tf32<1>, cudaFuncAttributeMaxDynamicSharedMemorySize, SMEM_BYTES);

    // h ping-pong buffers + c per layer chain
    float* h0buf[2] = { state,
                        state + (size_t)1 * BATCH * HD };
    float* c0      =   state + (size_t)2 * BATCH * HD;
    float* h1buf[2] = { state + (size_t)3 * BATCH * HD,
                        state + (size_t)4 * BATCH * HD };
    float* c1      =   state + (size_t)5 * BATCH * HD;

    // permuted weight layout inside g_wperm
    size_t off = 0;
    float* eWih0p = wperm + off; off += (size_t)FOURH * EDIM;
    float* eWhh0p = wperm + off; off += (size_t)FOURH * HD;
    float* eWih1p = wperm + off; off += (size_t)FOURH * HD;
    float* eWhh1p = wperm + off; off += (size_t)FOURH * HD;
    float* dWih0p = wperm + off; off += (size_t)FOURH * EDIM;
    float* dWhh0p = wperm + off; off += (size_t)FOURH * HD;
    float* dWih1p = wperm + off; off += (size_t)FOURH * HD;
    float* dWhh1p = wperm + off; off += (size_t)FOURH * HD;

    // ---- setup ----
    {
        int nE = FOURH * EDIM, nH = FOURH * HD;
        permW_k<<<(nE + 255) / 256, 256>>>(eW_ih0, eWih0p, EDIM);
        permW_k<<<(nH + 255) / 256, 256>>>(eW_hh0, eWhh0p, HD);
        permW_k<<<(nH + 255) / 256, 256>>>(eW_ih1, eWih1p, HD);
        permW_k<<<(nH + 255) / 256, 256>>>(eW_hh1, eWhh1p, HD);
        permW_k<<<(nE + 255) / 256, 256>>>(dW_ih0, dWih0p, EDIM);
        permW_k<<<(nH + 255) / 256, 256>>>(dW_hh0, dWhh0p, HD);
        permW_k<<<(nH + 255) / 256, 256>>>(dW_ih1, dWih1p, HD);
        permW_k<<<(nH + 255) / 256, 256>>>(dW_hh1, dWhh1p, HD);
        permB_k<<<(4 * FOURH + 255) / 256, 256>>>(eb_ih0, eb_hh0, eb_ih1, eb_hh1,
                                                  db_ih0, db_hh0, db_ih1, db_hh1, bsum);
        embr_k<<<(VOCAB * EDIM + 255) / 256, 256>>>(emb, embr);
        int n4 = 6 * BATCH * HD / 4;
        zero_k<<<(n4 + 255) / 256, 256>>>(state, n4);
        build_dectok_k<<<(BATCH * SEQ + 255) / 256, 256>>>(tgt, dectok);
    }

    const dim3 gBig(FOURH / BN, MROWS / BM);   // (32, 384)
    const dim3 gRec(FOURH / BN, BATCH / BM);   // (32, 16)

    // ===== encoder layer 0 =====
    gemm_tf32<0><<<gBig, 128, SMEM_BYTES>>>(embr, src, eWih0p, bsum + 0 * FOURH, nullptr, Xg,
                                            nullptr, nullptr, nullptr, 0, EDIM, 0);
    for (int t = 0; t < SEQ; ++t)
        gemm_tf32<1><<<gRec, 128, SMEM_BYTES>>>(h0buf[t & 1], nullptr, eWhh0p, nullptr, Xg, nullptr,
                                                h0buf[(t + 1) & 1], c0, y, 1, HD, t);
    // ===== encoder layer 1 =====
    gemm_tf32<0><<<gBig, 128, SMEM_BYTES>>>(y, nullptr, eWih1p, bsum + 1 * FOURH, nullptr, Xg,
                                            nullptr, nullptr, nullptr, 0, HD, 0);
    for (int t = 0; t < SEQ; ++t)
        gemm_tf32<1><<<gRec, 128, SMEM_BYTES>>>(h1buf[t & 1], nullptr, eWhh1p, nullptr, Xg, nullptr,
                                                h1buf[(t + 1) & 1], c1, nullptr, 0, HD, t);
    // ===== decoder layer 0 (SEQ even -> encoder-final h is back in buf[0]) =====
    gemm_tf32<0><<<gBig, 128, SMEM_BYTES>>>(embr, dectok, dWih0p, bsum + 2 * FOURH, nullptr, Xg,
                                            nullptr, nullptr, nullptr, 0, EDIM, 0);
    for (int t = 0; t < SEQ; ++t)
        gemm_tf32<1><<<gRec, 128, SMEM_BYTES>>>(h0buf[t & 1], nullptr, dWhh0p, nullptr, Xg, nullptr,
                                                h0buf[(t + 1) & 1], c0, y, 1, HD, t);
    // ===== decoder layer 1 =====
    gemm_tf32<0><<<gBig, 128, SMEM_BYTES>>>(y, nullptr, dWih1p, bsum + 3 * FOURH, nullptr, Xg,
                                            nullptr, nullptr, nullptr, 0, HD, 0);
    for (int t = 0; t < SEQ; ++t)
        gemm_tf32<1><<<gRec, 128, SMEM_BYTES>>>(h1buf[t & 1], nullptr, dWhh1p, nullptr, Xg, nullptr,
                                                h1buf[(t + 1) & 1], c1, y, 1, HD, t);
    // ===== output projection =====
    proj_k<<<MROWS / 128, 256>>>(y, fcW, fcb, out);
}

// round 13
// speedup vs baseline: 1.1571x; 1.1410x over previous
#include <cuda_runtime.h>
#include <cstdint>
#include <math.h>

// ---------------- problem constants ----------------
#define HD     1024
#define FOURH  4096
#define BATCH  2048
#define SEQ    24
#define EDIM   256
#define VOCAB  37
#define MROWS  (BATCH*SEQ)   // 49152

// ---------------- device scratch (no allocation allowed) ----------------
__device__ float g_Xg[(size_t)MROWS * FOURH];      // input projections (gate-interleaved cols)
__device__ float g_y[(size_t)MROWS * HD];          // per-layer outputs (tf32-rounded)
__device__ float g_state[(size_t)6 * BATCH * HD];  // h0a,h0b,c0,h1a,h1b,c1
__device__ float g_wperm[(size_t)2*4096*256 + (size_t)6*4096*1024]; // permuted+rounded weights
__device__ float g_bsum[4 * FOURH];
__device__ float g_embr[VOCAB * EDIM];
__device__ int   g_dectok[BATCH * SEQ];

// ---------------- helpers ----------------
__device__ __forceinline__ float tf32r(float x) {
    uint32_t r;
    asm("cvt.rna.tf32.f32 %0, %1;" : "=r"(r) : "f"(x));
    return __uint_as_float(r);
}
__device__ __forceinline__ float fsig(float x)  { return __fdividef(1.f, 1.f + __expf(-x)); }
__device__ __forceinline__ float ftanh(float x) { return __fdividef(2.f, 1.f + __expf(-2.f * x)) - 1.f; }

__device__ __forceinline__ void mma_tf32(float* c, const uint32_t* a, const uint32_t* b) {
    asm volatile(
        "mma.sync.aligned.m16n8k8.row.col.f32.tf32.tf32.f32 "
        "{%0,%1,%2,%3}, {%4,%5,%6,%7}, {%8,%9}, {%0,%1,%2,%3};\n"
        : "+f"(c[0]), "+f"(c[1]), "+f"(c[2]), "+f"(c[3])
        : "r"(a[0]), "r"(a[1]), "r"(a[2]), "r"(a[3]), "r"(b[0]), "r"(b[1]));
}
// ldmatrix x4 on 32-bit elements: lane l of each m8n8 matrix gets tf32 (row l/4, col l%4)
__device__ __forceinline__ void ldsm4(uint32_t* r, uint32_t addr) {
    asm volatile("ldmatrix.sync.aligned.m8n8.x4.shared.b16 {%0,%1,%2,%3}, [%4];"
        : "=r"(r[0]), "=r"(r[1]), "=r"(r[2]), "=r"(r[3]) : "r"(addr));
}
__device__ __forceinline__ void cp16(void* s, const void* g) {
    uint32_t sa = (uint32_t)__cvta_generic_to_shared(s);
    asm volatile("cp.async.ca.shared.global [%0], [%1], 16;\n" :: "r"(sa), "l"(g));
}
#define CP_COMMIT() asm volatile("cp.async.commit_group;\n" ::)
#define CP_WAIT(n)  asm volatile("cp.async.wait_group %0;\n" :: "n"(n))

// ---------------- GEMM: C[M,4096] = A[M,K] @ Wp[4096,K]^T (+ fused epilogue) ----------------
// Weights gate-interleaved (row r' = 4u+g), all operands pre-rounded to tf32.
// MODE 0: input projection (+bsum). MODE 1: recurrent step + fused LSTM cell;
//   h read from ping-pong buffer A, new h written to hW (other buffer) -> no race.
// Frag loads via ldmatrix.x4; 4-stage cp.async pipeline, one __syncthreads per k-iter.
constexpr int BM = 128, BN = 128, BK = 16, SPAD = 4;  // row stride 20 floats (80B) -> ldmatrix conflict-free
constexpr int STAGES = 4;
constexpr int ROWB = (BK + SPAD) * 4;                  // 80 bytes per smem row
constexpr int ABUF = BM * ROWB;                        // bytes per A stage
constexpr int BBUF = BN * ROWB;                        // bytes per B stage
constexpr int SMEM_BYTES = STAGES * (ABUF + BBUF);     // 81920

template<int MODE>
__global__ __launch_bounds__(128)
void gemm_tf32(const float* __restrict__ A, const int* __restrict__ tok,
               const float* __restrict__ W,
               const float* __restrict__ bsum,
               const float* __restrict__ Xg,
               float* __restrict__ C,          // MODE0 out
               float* __restrict__ hW, float* __restrict__ cP,  // MODE1
               float* __restrict__ yP, int writeY,
               int K, int t)
{
    extern __shared__ float smem[];
    float (*sA)[BM][BK + SPAD] = (float (*)[BM][BK + SPAD])smem;
    float (*sB)[BN][BK + SPAD] = (float (*)[BN][BK + SPAD])(smem + STAGES * BM * (BK + SPAD));
    const uint32_t sAb = (uint32_t)__cvta_generic_to_shared(&sA[0][0][0]);
    const uint32_t sBb = (uint32_t)__cvta_generic_to_shared(&sB[0][0][0]);

    const int tid  = threadIdx.x;
    const int bm   = blockIdx.y * BM;
    const int bn   = blockIdx.x * BN;
    const int ldr  = tid >> 2;          // 0..31
    const int ldc  = (tid & 3) * 4;     // 0,4,8,12

    // loader base pointers (token gather folded in)
    const float* abase[4];
    const float* bbase[4];
#pragma unroll
    for (int i = 0; i < 4; ++i) {
        int m = bm + ldr + i * 32;
        const float* base = tok ? (A + (size_t)tok[m] * K) : (A + (size_t)m * K);
        abase[i] = base + ldc;
        bbase[i] = W + (size_t)(bn + ldr + i * 32) * K + ldc;
    }

    const int KT = K / BK;

    // prologue: stages 0..STAGES-2 in flight
#pragma unroll
    for (int s = 0; s < STAGES - 1; ++s) {
        if (s < KT) {
#pragma unroll
            for (int i = 0; i < 4; ++i) cp16(&sA[s][ldr + i * 32][ldc], abase[i] + s * BK);
#pragma unroll
            for (int i = 0; i < 4; ++i) cp16(&sB[s][ldr + i * 32][ldc], bbase[i] + s * BK);
        }
        CP_COMMIT();
    }

    const int wid  = tid >> 5;
    const int lane = tid & 31;
    const int wm   = (wid >> 1) * 64;   // warp M offset
    const int wn   = (wid & 1) * 64;    // warp N offset
    const int lr   = lane >> 2;         // 0..7
    const int lc   = lane & 3;          // 0..3

    // ldmatrix lane-address components
    const int lrowA = ((lane >> 3) & 1) * 8 + (lane & 7);   // matrices: (r,c),(r+8,c),(r,c+4),(r+8,c+4)
    const int lcolA = (lane >> 4) * 4;
    const int lrowB = (lane >> 4) * 8 + (lane & 7);         // matrices: (n,k),(n,k+4),(n+8,k),(n+8,k+4)
    const int lcolB = ((lane >> 3) & 1) * 4;
    const uint32_t aAddr0 = sAb + (uint32_t)((wm + lrowA) * ROWB + lcolA * 4);
    const uint32_t bAddr0 = sBb + (uint32_t)((wn + lrowB) * ROWB + lcolB * 4);

    float acc[4][8][4];
#pragma unroll
    for (int a = 0; a < 4; ++a)
#pragma unroll
        for (int b = 0; b < 8; ++b)
#pragma unroll
            for (int q = 0; q < 4; ++q) acc[a][b][q] = 0.f;

    for (int kt = 0; kt < KT; ++kt) {
        CP_WAIT(STAGES - 2);
        __syncthreads();
        const int buf = kt & (STAGES - 1);
        const uint32_t aS = aAddr0 + (uint32_t)(buf * ABUF);
        const uint32_t bS = bAddr0 + (uint32_t)(buf * BBUF);
#pragma unroll
        for (int ks = 0; ks < 2; ++ks) {
            const uint32_t kOff = (uint32_t)(ks * 32);      // 8 floats
            uint32_t af[4][4], bq[4][4];
#pragma unroll
            for (int mt = 0; mt < 4; ++mt)
                ldsm4(af[mt], aS + (uint32_t)(mt * 16 * ROWB) + kOff);
#pragma unroll
            for (int np = 0; np < 4; ++np)
                ldsm4(bq[np], bS + (uint32_t)(np * 16 * ROWB) + kOff);
#pragma unroll
            for (int mt = 0; mt < 4; ++mt)
#pragma unroll
                for (int nt = 0; nt < 8; ++nt)
                    mma_tf32(acc[mt][nt], af[mt], &bq[nt >> 1][(nt & 1) * 2]);
        }
        const int pt = kt + STAGES - 1;
        if (pt < KT) {
            const int ps = pt & (STAGES - 1);
#pragma unroll
            for (int i = 0; i < 4; ++i) cp16(&sA[ps][ldr + i * 32][ldc], abase[i] + pt * BK);
#pragma unroll
            for (int i = 0; i < 4; ++i) cp16(&sB[ps][ldr + i * 32][ldc], bbase[i] + pt * BK);
        }
        CP_COMMIT();
    }

    // ---------------- epilogue ----------------
#pragma unroll
    for (int mt = 0; mt < 4; ++mt) {
        const int gr0 = bm + wm + mt * 16 + lr;
        const int gr1 = gr0 + 8;
#pragma unroll
        for (int nt = 0; nt < 8; ++nt) {
            const int gc = bn + wn + nt * 8 + lc * 2;
            if (MODE == 0) {
                float bx = bsum[gc], by = bsum[gc + 1];
                float2 v0, v1;
                v0.x = acc[mt][nt][0] + bx; v0.y = acc[mt][nt][1] + by;
                v1.x = acc[mt][nt][2] + bx; v1.y = acc[mt][nt][3] + by;
                *(float2*)&C[(size_t)gr0 * FOURH + gc] = v0;
                *(float2*)&C[(size_t)gr1 * FOURH + gc] = v1;
            } else {
                // gates = acc + Xg ; interleaved cols: even lane -> (i,f), odd lane -> (g,o)
                float2 x0 = *(const float2*)&Xg[((size_t)gr0 * SEQ + t) * FOURH + gc];
                float2 x1 = *(const float2*)&Xg[((size_t)gr1 * SEQ + t) * FOURH + gc];
                float v0 = acc[mt][nt][0] + x0.x;
                float v1 = acc[mt][nt][1] + x0.y;
                float v2 = acc[mt][nt][2] + x1.x;
                float v3 = acc[mt][nt][3] + x1.y;
                float p0 = __shfl_xor_sync(0xffffffffu, v0, 1);
                float p1 = __shfl_xor_sync(0xffffffffu, v1, 1);
                float p2 = __shfl_xor_sync(0xffffffffu, v2, 1);
                float p3 = __shfl_xor_sync(0xffffffffu, v3, 1);
                if ((lane & 1) == 0) {
                    const int u = gc >> 2;
                    const size_t cb0 = (size_t)gr0 * HD + u;
                    const size_t cb1 = (size_t)gr1 * HD + u;
                    float c0 = cP[cb0], c1 = cP[cb1];
                    c0 = fsig(v1) * c0 + fsig(v0) * ftanh(p0);
                    c1 = fsig(v3) * c1 + fsig(v2) * ftanh(p2);
                    float h0 = fsig(p1) * ftanh(c0);
                    float h1 = fsig(p3) * ftanh(c1);
                    cP[cb0] = c0; cP[cb1] = c1;
                    h0 = tf32r(h0); h1 = tf32r(h1);
                    hW[cb0] = h0; hW[cb1] = h1;
                    if (writeY) {
                        yP[((size_t)gr0 * SEQ + t) * HD + u] = h0;
                        yP[((size_t)gr1 * SEQ + t) * HD + u] = h1;
                    }
                }
            }
        }
    }
}

// ---------------- setup kernels ----------------
__global__ void permW_k(const float* __restrict__ in, float* __restrict__ out, int K)
{
    int idx = blockIdx.x * blockDim.x + threadIdx.x;
    if (idx < FOURH * K) {
        int rp = idx / K, k = idx - rp * K;
        int orig = (rp & 3) * HD + (rp >> 2);
        out[idx] = tf32r(in[orig * K + k]);
    }
}

__global__ void permB_k(const float* bi0, const float* bh0, const float* bi1, const float* bh1,
                        const float* bi2, const float* bh2, const float* bi3, const float* bh3,
                        float* __restrict__ out)
{
    int idx = blockIdx.x * blockDim.x + threadIdx.x;
    if (idx < 4 * FOURH) {
        int l = idx >> 12, rp = idx & (FOURH - 1);
        int orig = (rp & 3) * HD + (rp >> 2);
        const float* bi = (l == 0) ? bi0 : (l == 1) ? bi1 : (l == 2) ? bi2 : bi3;
        const float* bh = (l == 0) ? bh0 : (l == 1) ? bh1 : (l == 2) ? bh2 : bh3;
        out[idx] = bi[orig] + bh[orig];
    }
}

__global__ void embr_k(const float* __restrict__ emb, float* __restrict__ out)
{
    int i = blockIdx.x * blockDim.x + threadIdx.x;
    if (i < VOCAB * EDIM) out[i] = tf32r(emb[i]);
}

__global__ void zero_k(float* p, int n4)
{
    int i = blockIdx.x * blockDim.x + threadIdx.x;
    if (i < n4) ((float4*)p)[i] = make_float4(0.f, 0.f, 0.f, 0.f);
}

__global__ void build_dectok_k(const int* __restrict__ tgt, int* __restrict__ dt)
{
    int idx = blockIdx.x * blockDim.x + threadIdx.x;
    if (idx < BATCH * SEQ) {
        int b = idx / SEQ, t = idx - b * SEQ;
        dt[idx] = (t == 0) ? 1 : tgt[b * SEQ + t - 1];
    }
}

// ---------------- output projection: out[M,37] = y[M,1024] @ fcW[37,1024]^T + fcb ----------------
__global__ __launch_bounds__(256)
void proj_k(const float* __restrict__ y, const float* __restrict__ fcW,
            const float* __restrict__ fcb, float* __restrict__ out)
{
    __shared__ float ys[128][65];
    __shared__ float ws[40][65];
    const int tid = threadIdx.x;
    const int gm0 = blockIdx.x * 128;
    const int r0  = (tid >> 3) * 4;
    const int n0  = (tid & 7) * 5;

    float acc[4][5];
#pragma unroll
    for (int i = 0; i < 4; ++i)
#pragma unroll
        for (int j = 0; j < 5; ++j) acc[i][j] = 0.f;

    for (int kc = 0; kc < 16; ++kc) {
        __syncthreads();
        for (int i = tid; i < 128 * 16; i += 256) {
            int r = i >> 4, c4 = (i & 15) * 4;
            float4 v = *(const float4*)&y[(size_t)(gm0 + r) * HD + kc * 64 + c4];
            ys[r][c4] = v.x; ys[r][c4 + 1] = v.y; ys[r][c4 + 2] = v.z; ys[r][c4 + 3] = v.w;
        }
        for (int i = tid; i < 40 * 64; i += 256) {
            int n = i >> 6, cc = i & 63;
            ws[n][cc] = (n < VOCAB) ? fcW[n * HD + kc * 64 + cc] : 0.f;
        }
        __syncthreads();
#pragma unroll 8
        for (int k = 0; k < 64; ++k) {
            float yv[4], wv[5];
#pragma unroll
            for (int i = 0; i < 4; ++i) yv[i] = ys[r0 + i][k];
#pragma unroll
            for (int j = 0; j < 5; ++j) wv[j] = ws[n0 + j][k];
#pragma unroll
            for (int i = 0; i < 4; ++i)
#pragma unroll
                for (int j = 0; j < 5; ++j) acc[i][j] += yv[i] * wv[j];
        }
    }
#pragma unroll
    for (int i = 0; i < 4; ++i)
#pragma unroll
        for (int j = 0; j < 5; ++j) {
            int n = n0 + j;
            if (n < VOCAB)
                out[(size_t)(gm0 + r0 + i) * VOCAB + n] = acc[i][j] + fcb[n];
        }
}

// ---------------- host driver ----------------
extern "C" void kernel_launch(void* const* d_in, const int* in_sizes, int n_in,
                              void* d_out, int out_size)
{
    const int*   src    = (const int*)d_in[0];
    const int*   tgt    = (const int*)d_in[1];
    const float* emb    = (const float*)d_in[2];
    const float* eW_ih0 = (const float*)d_in[3];
    const float* eW_hh0 = (const float*)d_in[4];
    const float* eb_ih0 = (const float*)d_in[5];
    const float* eb_hh0 = (const float*)d_in[6];
    const float* eW_ih1 = (const float*)d_in[7];
    const float* eW_hh1 = (const float*)d_in[8];
    const float* eb_ih1 = (const float*)d_in[9];
    const float* eb_hh1 = (const float*)d_in[10];
    const float* dW_ih0 = (const float*)d_in[11];
    const float* dW_hh0 = (const float*)d_in[12];
    const float* db_ih0 = (const float*)d_in[13];
    const float* db_hh0 = (const float*)d_in[14];
    const float* dW_ih1 = (const float*)d_in[15];
    const float* dW_hh1 = (const float*)d_in[16];
    const float* db_ih1 = (const float*)d_in[17];
    const float* db_hh1 = (const float*)d_in[18];
    const float* fcW    = (const float*)d_in[19];
    const float* fcb    = (const float*)d_in[20];
    float* out = (float*)d_out;

    float *Xg, *y, *state, *wperm, *bsum, *embr;
    int*   dectok;
    cudaGetSymbolAddress((void**)&Xg,     g_Xg);
    cudaGetSymbolAddress((void**)&y,      g_y);
    cudaGetSymbolAddress((void**)&state,  g_state);
    cudaGetSymbolAddress((void**)&wperm,  g_wperm);
    cudaGetSymbolAddress((void**)&bsum,   g_bsum);
    cudaGetSymbolAddress((void**)&embr,   g_embr);
    cudaGetSymbolAddress((void**)&dectok, g_dectok);

    cudaFuncSetAttribute(gemm_tf32<0>, cudaFuncAttributeMaxDynamicSharedMemorySize, SMEM_BYTES);
    cudaFuncSetAttribute(gemm_tf32<1>, cudaFuncAttributeMaxDynamicSharedMemorySize, SMEM_BYTES);

    // h ping-pong buffers + c per layer
    float* h0buf[2] = { state,
                        state + (size_t)1 * BATCH * HD };
    float* c0      =   state + (size_t)2 * BATCH * HD;
    float* h1buf[2] = { state + (size_t)3 * BATCH * HD,
                        state + (size_t)4 * BATCH * HD };
    float* c1      =   state + (size_t)5 * BATCH * HD;

    size_t off = 0;
    float* eWih0p = wperm + off; off += (size_t)FOURH * EDIM;
    float* eWhh0p = wperm + off; off += (size_t)FOURH * HD;
    float* eWih1p = wperm + off; off += (size_t)FOURH * HD;
    float* eWhh1p = wperm + off; off += (size_t)FOURH * HD;
    float* dWih0p = wperm + off; off += (size_t)FOURH * EDIM;
    float* dWhh0p = wperm + off; off += (size_t)FOURH * HD;
    float* dWih1p = wperm + off; off += (size_t)FOURH * HD;
    float* dWhh1p = wperm + off; off += (size_t)FOURH * HD;

    // ---- setup ----
    {
        int nE = FOURH * EDIM, nH = FOURH * HD;
        permW_k<<<(nE + 255) / 256, 256>>>(eW_ih0, eWih0p, EDIM);
        permW_k<<<(nH + 255) / 256, 256>>>(eW_hh0, eWhh0p, HD);
        permW_k<<<(nH + 255) / 256, 256>>>(eW_ih1, eWih1p, HD);
        permW_k<<<(nH + 255) / 256, 256>>>(eW_hh1, eWhh1p, HD);
        permW_k<<<(nE + 255) / 256, 256>>>(dW_ih0, dWih0p, EDIM);
        permW_k<<<(nH + 255) / 256, 256>>>(dW_hh0, dWhh0p, HD);
        permW_k<<<(nH + 255) / 256, 256>>>(dW_ih1, dWih1p, HD);
        permW_k<<<(nH + 255) / 256, 256>>>(dW_hh1, dWhh1p, HD);
        permB_k<<<(4 * FOURH + 255) / 256, 256>>>(eb_ih0, eb_hh0, eb_ih1, eb_hh1,
                                                  db_ih0, db_hh0, db_ih1, db_hh1, bsum);
        embr_k<<<(VOCAB * EDIM + 255) / 256, 256>>>(emb, embr);
        int n4 = 6 * BATCH * HD / 4;
        zero_k<<<(n4 + 255) / 256, 256>>>(state, n4);
        build_dectok_k<<<(BATCH * SEQ + 255) / 256, 256>>>(tgt, dectok);
    }

    const dim3 gBig(FOURH / BN, MROWS / BM);   // (32, 384)
    const dim3 gRec(FOURH / BN, BATCH / BM);   // (32, 16)

    // ===== encoder layer 0 =====
    gemm_tf32<0><<<gBig, 128, SMEM_BYTES>>>(embr, src, eWih0p, bsum + 0 * FOURH, nullptr, Xg,
                                            nullptr, nullptr, nullptr, 0, EDIM, 0);
    for (int t = 0; t < SEQ; ++t)
        gemm_tf32<1><<<gRec, 128, SMEM_BYTES>>>(h0buf[t & 1], nullptr, eWhh0p, nullptr, Xg, nullptr,
                                                h0buf[(t + 1) & 1], c0, y, 1, HD, t);
    // ===== encoder layer 1 =====
    gemm_tf32<0><<<gBig, 128, SMEM_BYTES>>>(y, nullptr, eWih1p, bsum + 1 * FOURH, nullptr, Xg,
                                            nullptr, nullptr, nullptr, 0, HD, 0);
    for (int t = 0; t < SEQ; ++t)
        gemm_tf32<1><<<gRec, 128, SMEM_BYTES>>>(h1buf[t & 1], nullptr, eWhh1p, nullptr, Xg, nullptr,
                                                h1buf[(t + 1) & 1], c1, nullptr, 0, HD, t);
    // ===== decoder layer 0 (SEQ even -> encoder-final h back in buf[0]) =====
    gemm_tf32<0><<<gBig, 128, SMEM_BYTES>>>(embr, dectok, dWih0p, bsum + 2 * FOURH, nullptr, Xg,
                                            nullptr, nullptr, nullptr, 0, EDIM, 0);
    for (int t = 0; t < SEQ; ++t)
        gemm_tf32<1><<<gRec, 128, SMEM_BYTES>>>(h0buf[t & 1], nullptr, dWhh0p, nullptr, Xg, nullptr,
                                                h0buf[(t + 1) & 1], c0, y, 1, HD, t);
    // ===== decoder layer 1 =====
    gemm_tf32<0><<<gBig, 128, SMEM_BYTES>>>(y, nullptr, dWih1p, bsum + 3 * FOURH, nullptr, Xg,
                                            nullptr, nullptr, nullptr, 0, HD, 0);
    for (int t = 0; t < SEQ; ++t)
        gemm_tf32<1><<<gRec, 128, SMEM_BYTES>>>(h1buf[t & 1], nullptr, dWhh1p, nullptr, Xg, nullptr,
                                                h1buf[(t + 1) & 1], c1, y, 1, HD, t);
    // ===== output projection =====
    proj_k<<<MROWS / 128, 256>>>(y, fcW, fcb, out);
}

// round 14
// speedup vs baseline: 1.1604x; 1.0029x over previous
#include <cuda_runtime.h>
#include <cstdint>
#include <math.h>

// ---------------- problem constants ----------------
#define HD     1024
#define FOURH  4096
#define BATCH  2048
#define SEQ    24
#define EDIM   256
#define VOCAB  37
#define MROWS  (BATCH*SEQ)   // 49152

// ---------------- device scratch (no allocation allowed) ----------------
__device__ float g_Xg[(size_t)MROWS * FOURH];      // input projections (gate-interleaved cols)
__device__ float g_y[(size_t)MROWS * HD];          // per-layer outputs (tf32-rounded)
__device__ float g_state[(size_t)6 * BATCH * HD];  // h0a,h0b,c0,h1a,h1b,c1
__device__ float g_wperm[(size_t)2*4096*256 + (size_t)6*4096*1024]; // permuted+rounded weights
__device__ float g_bsum[4 * FOURH];
__device__ float g_embr[VOCAB * EDIM];
__device__ int   g_dectok[BATCH * SEQ];

// ---------------- helpers ----------------
__device__ __forceinline__ float tf32r(float x) {
    uint32_t r;
    asm("cvt.rna.tf32.f32 %0, %1;" : "=r"(r) : "f"(x));
    return __uint_as_float(r);
}
__device__ __forceinline__ float fsig(float x)  { return __fdividef(1.f, 1.f + __expf(-x)); }
__device__ __forceinline__ float ftanh(float x) { return __fdividef(2.f, 1.f + __expf(-2.f * x)) - 1.f; }

__device__ __forceinline__ void mma_tf32(float* c, const uint32_t* a, const uint32_t* b) {
    asm volatile(
        "mma.sync.aligned.m16n8k8.row.col.f32.tf32.tf32.f32 "
        "{%0,%1,%2,%3}, {%4,%5,%6,%7}, {%8,%9}, {%0,%1,%2,%3};\n"
        : "+f"(c[0]), "+f"(c[1]), "+f"(c[2]), "+f"(c[3])
        : "r"(a[0]), "r"(a[1]), "r"(a[2]), "r"(a[3]), "r"(b[0]), "r"(b[1]));
}
// ldmatrix x4 on 32-bit elems: validated mapping (R13) for both A and B frags
__device__ __forceinline__ void ldsm4(uint32_t* r, uint32_t addr) {
    asm volatile("ldmatrix.sync.aligned.m8n8.x4.shared.b16 {%0,%1,%2,%3}, [%4];"
        : "=r"(r[0]), "=r"(r[1]), "=r"(r[2]), "=r"(r[3]) : "r"(addr));
}
__device__ __forceinline__ void cp16(void* s, const void* g) {
    uint32_t sa = (uint32_t)__cvta_generic_to_shared(s);
    asm volatile("cp.async.ca.shared.global [%0], [%1], 16;\n" :: "r"(sa), "l"(g));
}
#define CP_COMMIT() asm volatile("cp.async.commit_group;\n" ::)
#define CP_WAIT(n)  asm volatile("cp.async.wait_group %0;\n" :: "n"(n))

// ---------------- GEMM: C[M,4096] = A[M,K] @ Wp[4096,K]^T (+ fused epilogue) ----------------
// CTA tile 128x256, 256 threads, 8 warps (2M x 4N), warp tile 64x64. BK=16, 4-stage cp.async,
// one __syncthreads per k-iter, frag double-buffering across the two 8-k halves.
// MODE 0: input projection (+bsum). MODE 1: recurrent step + fused LSTM cell (h ping-pong).
constexpr int BM = 128, BN = 256, BK = 16, SPAD = 4;  // row stride 20 floats -> ldmatrix conflict-free
constexpr int STAGES = 4;
constexpr int ROWB = (BK + SPAD) * 4;                  // 80 B per smem row
constexpr int ABUF = BM * ROWB;                        // 10240 B / stage
constexpr int BBUF = BN * ROWB;                        // 20480 B / stage
constexpr int SMEM_BYTES = STAGES * (ABUF + BBUF);     // 122880

template<int MODE>
__global__ __launch_bounds__(256)
void gemm_tf32(const float* __restrict__ A, const int* __restrict__ tok,
               const float* __restrict__ W,
               const float* __restrict__ bsum,
               const float* __restrict__ Xg,
               float* __restrict__ C,          // MODE0 out
               float* __restrict__ hW, float* __restrict__ cP,  // MODE1
               float* __restrict__ yP, int writeY,
               int K, int t)
{
    extern __shared__ float smem[];
    float (*sA)[BM][BK + SPAD] = (float (*)[BM][BK + SPAD])smem;
    float (*sB)[BN][BK + SPAD] = (float (*)[BN][BK + SPAD])(smem + STAGES * BM * (BK + SPAD));
    const uint32_t sAb = (uint32_t)__cvta_generic_to_shared(&sA[0][0][0]);
    const uint32_t sBb = (uint32_t)__cvta_generic_to_shared(&sB[0][0][0]);

    const int tid  = threadIdx.x;
    const int bm   = blockIdx.y * BM;
    const int bn   = blockIdx.x * BN;
    const int ldr  = tid >> 2;          // 0..63
    const int ldc  = (tid & 3) * 4;     // 0,4,8,12

    // loader base pointers: 2 A rows + 4 B rows per thread
    const float* abase[2];
    const float* bbase[4];
#pragma unroll
    for (int i = 0; i < 2; ++i) {
        int m = bm + ldr + i * 64;
        const float* base = tok ? (A + (size_t)tok[m] * K) : (A + (size_t)m * K);
        abase[i] = base + ldc;
    }
#pragma unroll
    for (int i = 0; i < 4; ++i)
        bbase[i] = W + (size_t)(bn + ldr + i * 64) * K + ldc;

    const int KT = K / BK;

    // prologue: stages 0..2 in flight
#pragma unroll
    for (int s = 0; s < STAGES - 1; ++s) {
        if (s < KT) {
#pragma unroll
            for (int i = 0; i < 2; ++i) cp16(&sA[s][ldr + i * 64][ldc], abase[i] + s * BK);
#pragma unroll
            for (int i = 0; i < 4; ++i) cp16(&sB[s][ldr + i * 64][ldc], bbase[i] + s * BK);
        }
        CP_COMMIT();
    }

    const int wid  = tid >> 5;
    const int lane = tid & 31;
    const int wm   = (wid >> 2) * 64;   // warp M offset (0,64)
    const int wn   = (wid & 3) * 64;    // warp N offset (0..192)
    const int lr   = lane >> 2;         // 0..7
    const int lc   = lane & 3;          // 0..3

    // ldmatrix lane addressing (validated in R13)
    const int lrowA = ((lane >> 3) & 1) * 8 + (lane & 7);
    const int lcolA = (lane >> 4) * 4;
    const int lrowB = (lane >> 4) * 8 + (lane & 7);
    const int lcolB = ((lane >> 3) & 1) * 4;
    const uint32_t aAddr0 = sAb + (uint32_t)((wm + lrowA) * ROWB + lcolA * 4);
    const uint32_t bAddr0 = sBb + (uint32_t)((wn + lrowB) * ROWB + lcolB * 4);

    float acc[4][8][4];
#pragma unroll
    for (int a = 0; a < 4; ++a)
#pragma unroll
        for (int b = 0; b < 8; ++b)
#pragma unroll
            for (int q = 0; q < 4; ++q) acc[a][b][q] = 0.f;

    for (int kt = 0; kt < KT; ++kt) {
        CP_WAIT(STAGES - 2);
        __syncthreads();
        const int buf = kt & (STAGES - 1);
        const uint32_t aS = aAddr0 + (uint32_t)(buf * ABUF);
        const uint32_t bS = bAddr0 + (uint32_t)(buf * BBUF);

        uint32_t af0[4][4], bq0[4][4], af1[4][4], bq1[4][4];
        // half 0 frags
#pragma unroll
        for (int mt = 0; mt < 4; ++mt) ldsm4(af0[mt], aS + (uint32_t)(mt * 16 * ROWB));
#pragma unroll
        for (int np = 0; np < 4; ++np) ldsm4(bq0[np], bS + (uint32_t)(np * 16 * ROWB));
        // issue next-stage global prefetch early (overlaps the MMAs below)
        const int pt = kt + STAGES - 1;
        if (pt < KT) {
            const int ps = pt & (STAGES - 1);
#pragma unroll
            for (int i = 0; i < 2; ++i) cp16(&sA[ps][ldr + i * 64][ldc], abase[i] + pt * BK);
#pragma unroll
            for (int i = 0; i < 4; ++i) cp16(&sB[ps][ldr + i * 64][ldc], bbase[i] + pt * BK);
        }
        CP_COMMIT();
        // half 1 frags (latency covered by half-0 MMAs)
#pragma unroll
        for (int mt = 0; mt < 4; ++mt) ldsm4(af1[mt], aS + (uint32_t)(mt * 16 * ROWB) + 32u);
#pragma unroll
        for (int np = 0; np < 4; ++np) ldsm4(bq1[np], bS + (uint32_t)(np * 16 * ROWB) + 32u);
#pragma unroll
        for (int mt = 0; mt < 4; ++mt)
#pragma unroll
            for (int nt = 0; nt < 8; ++nt)
                mma_tf32(acc[mt][nt], af0[mt], &bq0[nt >> 1][(nt & 1) * 2]);
#pragma unroll
        for (int mt = 0; mt < 4; ++mt)
#pragma unroll
            for (int nt = 0; nt < 8; ++nt)
                mma_tf32(acc[mt][nt], af1[mt], &bq1[nt >> 1][(nt & 1) * 2]);
    }

    // ---------------- epilogue ----------------
#pragma unroll
    for (int mt = 0; mt < 4; ++mt) {
        const int gr0 = bm + wm + mt * 16 + lr;
        const int gr1 = gr0 + 8;
#pragma unroll
        for (int nt = 0; nt < 8; ++nt) {
            const int gc = bn + wn + nt * 8 + lc * 2;
            if (MODE == 0) {
                float bx = bsum[gc], by = bsum[gc + 1];
                float2 v0, v1;
                v0.x = acc[mt][nt][0] + bx; v0.y = acc[mt][nt][1] + by;
                v1.x = acc[mt][nt][2] + bx; v1.y = acc[mt][nt][3] + by;
                *(float2*)&C[(size_t)gr0 * FOURH + gc] = v0;
                *(float2*)&C[(size_t)gr1 * FOURH + gc] = v1;
            } else {
                // gates = acc + Xg ; interleaved cols: even lane -> (i,f), odd lane -> (g,o)
                float2 x0 = *(const float2*)&Xg[((size_t)gr0 * SEQ + t) * FOURH + gc];
                float2 x1 = *(const float2*)&Xg[((size_t)gr1 * SEQ + t) * FOURH + gc];
                float v0 = acc[mt][nt][0] + x0.x;
                float v1 = acc[mt][nt][1] + x0.y;
                float v2 = acc[mt][nt][2] + x1.x;
                float v3 = acc[mt][nt][3] + x1.y;
                float p0 = __shfl_xor_sync(0xffffffffu, v0, 1);
                float p1 = __shfl_xor_sync(0xffffffffu, v1, 1);
                float p2 = __shfl_xor_sync(0xffffffffu, v2, 1);
                float p3 = __shfl_xor_sync(0xffffffffu, v3, 1);
                if ((lane & 1) == 0) {
                    const int u = gc >> 2;
                    const size_t cb0 = (size_t)gr0 * HD + u;
                    const size_t cb1 = (size_t)gr1 * HD + u;
                    float c0 = cP[cb0], c1 = cP[cb1];
                    c0 = fsig(v1) * c0 + fsig(v0) * ftanh(p0);
                    c1 = fsig(v3) * c1 + fsig(v2) * ftanh(p2);
                    float h0 = fsig(p1) * ftanh(c0);
                    float h1 = fsig(p3) * ftanh(c1);
                    cP[cb0] = c0; cP[cb1] = c1;
                    h0 = tf32r(h0); h1 = tf32r(h1);
                    hW[cb0] = h0; hW[cb1] = h1;
                    if (writeY) {
                        yP[((size_t)gr0 * SEQ + t) * HD + u] = h0;
                        yP[((size_t)gr1 * SEQ + t) * HD + u] = h1;
                    }
                }
            }
        }
    }
}

// ---------------- setup kernels ----------------
__global__ void permW_k(const float* __restrict__ in, float* __restrict__ out, int K)
{
    int idx = blockIdx.x * blockDim.x + threadIdx.x;
    if (idx < FOURH * K) {
        int rp = idx / K, k = idx - rp * K;
        int orig = (rp & 3) * HD + (rp >> 2);
        out[idx] = tf32r(in[orig * K + k]);
    }
}

__global__ void permB_k(const float* bi0, const float* bh0, const float* bi1, const float* bh1,
                        const float* bi2, const float* bh2, const float* bi3, const float* bh3,
                        float* __restrict__ out)
{
    int idx = blockIdx.x * blockDim.x + threadIdx.x;
    if (idx < 4 * FOURH) {
        int l = idx >> 12, rp = idx & (FOURH - 1);
        int orig = (rp & 3) * HD + (rp >> 2);
        const float* bi = (l == 0) ? bi0 : (l == 1) ? bi1 : (l == 2) ? bi2 : bi3;
        const float* bh = (l == 0) ? bh0 : (l == 1) ? bh1 : (l == 2) ? bh2 : bh3;
        out[idx] = bi[orig] + bh[orig];
    }
}

__global__ void embr_k(const float* __restrict__ emb, float* __restrict__ out)
{
    int i = blockIdx.x * blockDim.x + threadIdx.x;
    if (i < VOCAB * EDIM) out[i] = tf32r(emb[i]);
}

__global__ void zero_k(float* p, int n4)
{
    int i = blockIdx.x * blockDim.x + threadIdx.x;
    if (i < n4) ((float4*)p)[i] = make_float4(0.f, 0.f, 0.f, 0.f);
}

__global__ void build_dectok_k(const int* __restrict__ tgt, int* __restrict__ dt)
{
    int idx = blockIdx.x * blockDim.x + threadIdx.x;
    if (idx < BATCH * SEQ) {
        int b = idx / SEQ, t = idx - b * SEQ;
        dt[idx] = (t == 0) ? 1 : tgt[b * SEQ + t - 1];
    }
}

// ---------------- output projection: out[M,37] = y[M,1024] @ fcW[37,1024]^T + fcb ----------------
__global__ __launch_bounds__(256)
void proj_k(const float* __restrict__ y, const float* __restrict__ fcW,
            const float* __restrict__ fcb, float* __restrict__ out)
{
    __shared__ float ys[128][65];
    __shared__ float ws[40][65];
    const int tid = threadIdx.x;
    const int gm0 = blockIdx.x * 128;
    const int r0  = (tid >> 3) * 4;
    const int n0  = (tid & 7) * 5;

    float acc[4][5];
#pragma unroll
    for (int i = 0; i < 4; ++i)
#pragma unroll
        for (int j = 0; j < 5; ++j) acc[i][j] = 0.f;

    for (int kc = 0; kc < 16; ++kc) {
        __syncthreads();
        for (int i = tid; i < 128 * 16; i += 256) {
            int r = i >> 4, c4 = (i & 15) * 4;
            float4 v = *(const float4*)&y[(size_t)(gm0 + r) * HD + kc * 64 + c4];
            ys[r][c4] = v.x; ys[r][c4 + 1] = v.y; ys[r][c4 + 2] = v.z; ys[r][c4 + 3] = v.w;
        }
        for (int i = tid; i < 40 * 64; i += 256) {
            int n = i >> 6, cc = i & 63;
            ws[n][cc] = (n < VOCAB) ? fcW[n * HD + kc * 64 + cc] : 0.f;
        }
        __syncthreads();
#pragma unroll 8
        for (int k = 0; k < 64; ++k) {
            float yv[4], wv[5];
#pragma unroll
            for (int i = 0; i < 4; ++i) yv[i] = ys[r0 + i][k];
#pragma unroll
            for (int j = 0; j < 5; ++j) wv[j] = ws[n0 + j][k];
#pragma unroll
            for (int i = 0; i < 4; ++i)
#pragma unroll
                for (int j = 0; j < 5; ++j) acc[i][j] += yv[i] * wv[j];
        }
    }
#pragma unroll
    for (int i = 0; i < 4; ++i)
#pragma unroll
        for (int j = 0; j < 5; ++j) {
            int n = n0 + j;
            if (n < VOCAB)
                out[(size_t)(gm0 + r0 + i) * VOCAB + n] = acc[i][j] + fcb[n];
        }
}

// ---------------- host driver ----------------
extern "C" void kernel_launch(void* const* d_in, const int* in_sizes, int n_in,
                              void* d_out, int out_size)
{
    const int*   src    = (const int*)d_in[0];
    const int*   tgt    = (const int*)d_in[1];
    const float* emb    = (const float*)d_in[2];
    const float* eW_ih0 = (const float*)d_in[3];
    const float* eW_hh0 = (const float*)d_in[4];
    const float* eb_ih0 = (const float*)d_in[5];
    const float* eb_hh0 = (const float*)d_in[6];
    const float* eW_ih1 = (const float*)d_in[7];
    const float* eW_hh1 = (const float*)d_in[8];
    const float* eb_ih1 = (const float*)d_in[9];
    const float* eb_hh1 = (const float*)d_in[10];
    const float* dW_ih0 = (const float*)d_in[11];
    const float* dW_hh0 = (const float*)d_in[12];
    const float* db_ih0 = (const float*)d_in[13];
    const float* db_hh0 = (const float*)d_in[14];
    const float* dW_ih1 = (const float*)d_in[15];
    const float* dW_hh1 = (const float*)d_in[16];
    const float* db_ih1 = (const float*)d_in[17];
    const float* db_hh1 = (const float*)d_in[18];
    const float* fcW    = (const float*)d_in[19];
    const float* fcb    = (const float*)d_in[20];
    float* out = (float*)d_out;

    float *Xg, *y, *state, *wperm, *bsum, *embr;
    int*   dectok;
    cudaGetSymbolAddress((void**)&Xg,     g_Xg);
    cudaGetSymbolAddress((void**)&y,      g_y);
    cudaGetSymbolAddress((void**)&state,  g_state);
    cudaGetSymbolAddress((void**)&wperm,  g_wperm);
    cudaGetSymbolAddress((void**)&bsum,   g_bsum);
    cudaGetSymbolAddress((void**)&embr,   g_embr);
    cudaGetSymbolAddress((void**)&dectok, g_dectok);

    cudaFuncSetAttribute(gemm_tf32<0>, cudaFuncAttributeMaxDynamicSharedMemorySize, SMEM_BYTES);
    cudaFuncSetAttribute(gemm_tf32<1>, cudaFuncAttributeMaxDynamicSharedMemorySize, SMEM_BYTES);

    // h ping-pong buffers + c per layer
    float* h0buf[2] = { state,
                        state + (size_t)1 * BATCH * HD };
    float* c0      =   state + (size_t)2 * BATCH * HD;
    float* h1buf[2] = { state + (size_t)3 * BATCH * HD,
                        state + (size_t)4 * BATCH * HD };
    float* c1      =   state + (size_t)5 * BATCH * HD;

    size_t off = 0;
    float* eWih0p = wperm + off; off += (size_t)FOURH * EDIM;
    float* eWhh0p = wperm + off; off += (size_t)FOURH * HD;
    float* eWih1p = wperm + off; off += (size_t)FOURH * HD;
    float* eWhh1p = wperm + off; off += (size_t)FOURH * HD;
    float* dWih0p = wperm + off; off += (size_t)FOURH * EDIM;
    float* dWhh0p = wperm + off; off += (size_t)FOURH * HD;
    float* dWih1p = wperm + off; off += (size_t)FOURH * HD;
    float* dWhh1p = wperm + off; off += (size_t)FOURH * HD;

    // ---- setup ----
    {
        int nE = FOURH * EDIM, nH = FOURH * HD;
        permW_k<<<(nE + 255) / 256, 256>>>(eW_ih0, eWih0p, EDIM);
        permW_k<<<(nH + 255) / 256, 256>>>(eW_hh0, eWhh0p, HD);
        permW_k<<<(nH + 255) / 256, 256>>>(eW_ih1, eWih1p, HD);
        permW_k<<<(nH + 255) / 256, 256>>>(eW_hh1, eWhh1p, HD);
        permW_k<<<(nE + 255) / 256, 256>>>(dW_ih0, dWih0p, EDIM);
        permW_k<<<(nH + 255) / 256, 256>>>(dW_hh0, dWhh0p, HD);
        permW_k<<<(nH + 255) / 256, 256>>>(dW_ih1, dWih1p, HD);
        permW_k<<<(nH + 255) / 256, 256>>>(dW_hh1, dWhh1p, HD);
        permB_k<<<(4 * FOURH + 255) / 256, 256>>>(eb_ih0, eb_hh0, eb_ih1, eb_hh1,
                                                  db_ih0, db_hh0, db_ih1, db_hh1, bsum);
        embr_k<<<(VOCAB * EDIM + 255) / 256, 256>>>(emb, embr);
        int n4 = 6 * BATCH * HD / 4;
        zero_k<<<(n4 + 255) / 256, 256>>>(state, n4);
        build_dectok_k<<<(BATCH * SEQ + 255) / 256, 256>>>(tgt, dectok);
    }

    const dim3 gBig(FOURH / BN, MROWS / BM);   // (16, 384)
    const dim3 gRec(FOURH / BN, BATCH / BM);   // (16, 16)

    // ===== encoder layer 0 =====
    gemm_tf32<0><<<gBig, 256, SMEM_BYTES>>>(embr, src, eWih0p, bsum + 0 * FOURH, nullptr, Xg,
                                            nullptr, nullptr, nullptr, 0, EDIM, 0);
    for (int t = 0; t < SEQ; ++t)
        gemm_tf32<1><<<gRec, 256, SMEM_BYTES>>>(h0buf[t & 1], nullptr, eWhh0p, nullptr, Xg, nullptr,
                                                h0buf[(t + 1) & 1], c0, y, 1, HD, t);
    // ===== encoder layer 1 =====
    gemm_tf32<0><<<gBig, 256, SMEM_BYTES>>>(y, nullptr, eWih1p, bsum + 1 * FOURH, nullptr, Xg,
                                            nullptr, nullptr, nullptr, 0, HD, 0);
    for (int t = 0; t < SEQ; ++t)
        gemm_tf32<1><<<gRec, 256, SMEM_BYTES>>>(h1buf[t & 1], nullptr, eWhh1p, nullptr, Xg, nullptr,
                                                h1buf[(t + 1) & 1], c1, nullptr, 0, HD, t);
    // ===== decoder layer 0 (SEQ even -> encoder-final h back in buf[0]) =====
    gemm_tf32<0><<<gBig, 256, SMEM_BYTES>>>(embr, dectok, dWih0p, bsum + 2 * FOURH, nullptr, Xg,
                                            nullptr, nullptr, nullptr, 0, EDIM, 0);
    for (int t = 0; t < SEQ; ++t)
        gemm_tf32<1><<<gRec, 256, SMEM_BYTES>>>(h0buf[t & 1], nullptr, dWhh0p, nullptr, Xg, nullptr,
                                                h0buf[(t + 1) & 1], c0, y, 1, HD, t);
    // ===== decoder layer 1 =====
    gemm_tf32<0><<<gBig, 256, SMEM_BYTES>>>(y, nullptr, dWih1p, bsum + 3 * FOURH, nullptr, Xg,
                                            nullptr, nullptr, nullptr, 0, HD, 0);
    for (int t = 0; t < SEQ; ++t)
        gemm_tf32<1><<<gRec, 256, SMEM_BYTES>>>(h1buf[t & 1], nullptr, dWhh1p, nullptr, Xg, nullptr,
                                                h1buf[(t + 1) & 1], c1, y, 1, HD, t);
    // ===== output projection =====
    proj_k<<<MROWS / 128, 256>>>(y, fcW, fcb, out);
}

// round 15
// speedup vs baseline: 1.2197x; 1.0511x over previous
#include <cuda_runtime.h>
#include <cstdint>
#include <math.h>

// ---------------- problem constants ----------------
#define HD     1024
#define FOURH  4096
#define BATCH  2048
#define SEQ    24
#define EDIM   256
#define VOCAB  37
#define MROWS  (BATCH*SEQ)   // 49152

// Global row order is T-MAJOR: r = t*BATCH + b  (BATCH = 2^11)

// ---------------- device scratch (no allocation allowed) ----------------
__device__ float g_Xg[(size_t)MROWS * FOURH];      // input projections (gate-interleaved cols, t-major rows)
__device__ float g_y[(size_t)MROWS * HD];          // per-layer outputs (tf32-rounded, t-major rows)
__device__ float g_state[(size_t)6 * BATCH * HD];  // h0a,h0b,c0,h1a,h1b,c1
__device__ float g_wperm[(size_t)2*4096*256 + (size_t)6*4096*1024]; // permuted+rounded weights
__device__ float g_bsum[4 * FOURH];
__device__ float g_embr[VOCAB * EDIM];
__device__ int   g_srct[MROWS];                    // t-major encoder tokens
__device__ int   g_dect[MROWS];                    // t-major decoder tokens

// ---------------- helpers ----------------
__device__ __forceinline__ float tf32r(float x) {
    uint32_t r;
    asm("cvt.rna.tf32.f32 %0, %1;" : "=r"(r) : "f"(x));
    return __uint_as_float(r);
}
__device__ __forceinline__ float fsig(float x)  { return __fdividef(1.f, 1.f + __expf(-x)); }
__device__ __forceinline__ float ftanh(float x) { return __fdividef(2.f, 1.f + __expf(-2.f * x)) - 1.f; }

__device__ __forceinline__ void mma_tf32(float* c, const uint32_t* a, const uint32_t* b) {
    asm volatile(
        "mma.sync.aligned.m16n8k8.row.col.f32.tf32.tf32.f32 "
        "{%0,%1,%2,%3}, {%4,%5,%6,%7}, {%8,%9}, {%0,%1,%2,%3};\n"
        : "+f"(c[0]), "+f"(c[1]), "+f"(c[2]), "+f"(c[3])
        : "r"(a[0]), "r"(a[1]), "r"(a[2]), "r"(a[3]), "r"(b[0]), "r"(b[1]));
}
__device__ __forceinline__ void ldsm4(uint32_t* r, uint32_t addr) {
    asm volatile("ldmatrix.sync.aligned.m8n8.x4.shared.b16 {%0,%1,%2,%3}, [%4];"
        : "=r"(r[0]), "=r"(r[1]), "=r"(r[2]), "=r"(r[3]) : "r"(addr));
}
__device__ __forceinline__ void cp16(void* s, const void* g) {
    uint32_t sa = (uint32_t)__cvta_generic_to_shared(s);
    asm volatile("cp.async.ca.shared.global [%0], [%1], 16;\n" :: "r"(sa), "l"(g));
}
#define CP_COMMIT() asm volatile("cp.async.commit_group;\n" ::)
#define CP_WAIT(n)  asm volatile("cp.async.wait_group %0;\n" :: "n"(n))

// ================= BIG input-projection GEMM (MODE 0 only) =================
// CTA 128x256, 256 thr, 8 warps (2Mx4N), warp 64x64, BK=16, 4 stages. (R14 shape)
constexpr int BM = 128, BN = 256, BK = 16, SPAD = 4;
constexpr int STAGES = 4;
constexpr int ROWB = (BK + SPAD) * 4;                  // 80 B per smem row
constexpr int ABUF = BM * ROWB;
constexpr int BBUF = BN * ROWB;
constexpr int SMEM_BYTES = STAGES * (ABUF + BBUF);     // 122880

__global__ __launch_bounds__(256)
void gemm_big(const float* __restrict__ A, const int* __restrict__ tok,
              const float* __restrict__ W, const float* __restrict__ bsum,
              float* __restrict__ C, int K)
{
    extern __shared__ float smem[];
    float (*sA)[BM][BK + SPAD] = (float (*)[BM][BK + SPAD])smem;
    float (*sB)[BN][BK + SPAD] = (float (*)[BN][BK + SPAD])(smem + STAGES * BM * (BK + SPAD));
    const uint32_t sAb = (uint32_t)__cvta_generic_to_shared(&sA[0][0][0]);
    const uint32_t sBb = (uint32_t)__cvta_generic_to_shared(&sB[0][0][0]);

    const int tid  = threadIdx.x;
    const int bm   = blockIdx.y * BM;
    const int bn   = blockIdx.x * BN;
    const int ldr  = tid >> 2;
    const int ldc  = (tid & 3) * 4;

    const float* abase[2];
    const float* bbase[4];
#pragma unroll
    for (int i = 0; i < 2; ++i) {
        int m = bm + ldr + i * 64;
        const float* base = tok ? (A + (size_t)tok[m] * K) : (A + (size_t)m * K);
        abase[i] = base + ldc;
    }
#pragma unroll
    for (int i = 0; i < 4; ++i)
        bbase[i] = W + (size_t)(bn + ldr + i * 64) * K + ldc;

    const int KT = K / BK;
#pragma unroll
    for (int s = 0; s < STAGES - 1; ++s) {
        if (s < KT) {
#pragma unroll
            for (int i = 0; i < 2; ++i) cp16(&sA[s][ldr + i * 64][ldc], abase[i] + s * BK);
#pragma unroll
            for (int i = 0; i < 4; ++i) cp16(&sB[s][ldr + i * 64][ldc], bbase[i] + s * BK);
        }
        CP_COMMIT();
    }

    const int wid  = tid >> 5;
    const int lane = tid & 31;
    const int wm   = (wid >> 2) * 64;
    const int wn   = (wid & 3) * 64;
    const int lr   = lane >> 2;
    const int lc   = lane & 3;

    const int lrowA = ((lane >> 3) & 1) * 8 + (lane & 7);
    const int lcolA = (lane >> 4) * 4;
    const int lrowB = (lane >> 4) * 8 + (lane & 7);
    const int lcolB = ((lane >> 3) & 1) * 4;
    const uint32_t aAddr0 = sAb + (uint32_t)((wm + lrowA) * ROWB + lcolA * 4);
    const uint32_t bAddr0 = sBb + (uint32_t)((wn + lrowB) * ROWB + lcolB * 4);

    float acc[4][8][4];
#pragma unroll
    for (int a = 0; a < 4; ++a)
#pragma unroll
        for (int b = 0; b < 8; ++b)
#pragma unroll
            for (int q = 0; q < 4; ++q) acc[a][b][q] = 0.f;

    for (int kt = 0; kt < KT; ++kt) {
        CP_WAIT(STAGES - 2);
        __syncthreads();
        const int buf = kt & (STAGES - 1);
        const uint32_t aS = aAddr0 + (uint32_t)(buf * ABUF);
        const uint32_t bS = bAddr0 + (uint32_t)(buf * BBUF);

        uint32_t af0[4][4], bq0[4][4], af1[4][4], bq1[4][4];
#pragma unroll
        for (int mt = 0; mt < 4; ++mt) ldsm4(af0[mt], aS + (uint32_t)(mt * 16 * ROWB));
#pragma unroll
        for (int np = 0; np < 4; ++np) ldsm4(bq0[np], bS + (uint32_t)(np * 16 * ROWB));
        const int pt = kt + STAGES - 1;
        if (pt < KT) {
            const int ps = pt & (STAGES - 1);
#pragma unroll
            for (int i = 0; i < 2; ++i) cp16(&sA[ps][ldr + i * 64][ldc], abase[i] + pt * BK);
#pragma unroll
            for (int i = 0; i < 4; ++i) cp16(&sB[ps][ldr + i * 64][ldc], bbase[i] + pt * BK);
        }
        CP_COMMIT();
#pragma unroll
        for (int mt = 0; mt < 4; ++mt) ldsm4(af1[mt], aS + (uint32_t)(mt * 16 * ROWB) + 32u);
#pragma unroll
        for (int np = 0; np < 4; ++np) ldsm4(bq1[np], bS + (uint32_t)(np * 16 * ROWB) + 32u);
#pragma unroll
        for (int mt = 0; mt < 4; ++mt)
#pragma unroll
            for (int nt = 0; nt < 8; ++nt)
                mma_tf32(acc[mt][nt], af0[mt], &bq0[nt >> 1][(nt & 1) * 2]);
#pragma unroll
        for (int mt = 0; mt < 4; ++mt)
#pragma unroll
            for (int nt = 0; nt < 8; ++nt)
                mma_tf32(acc[mt][nt], af1[mt], &bq1[nt >> 1][(nt & 1) * 2]);
    }

#pragma unroll
    for (int mt = 0; mt < 4; ++mt) {
        const int gr0 = bm + wm + mt * 16 + lr;
        const int gr1 = gr0 + 8;
#pragma unroll
        for (int nt = 0; nt < 8; ++nt) {
            const int gc = bn + wn + nt * 8 + lc * 2;
            float bx = bsum[gc], by = bsum[gc + 1];
            float2 v0, v1;
            v0.x = acc[mt][nt][0] + bx; v0.y = acc[mt][nt][1] + by;
            v1.x = acc[mt][nt][2] + bx; v1.y = acc[mt][nt][3] + by;
            *(float2*)&C[(size_t)gr0 * FOURH + gc] = v0;
            *(float2*)&C[(size_t)gr1 * FOURH + gc] = v1;
        }
    }
}

// ================= Recurrent GEMM + fused LSTM cell =================
// CTA 64x128, 128 thr, 4 warps (2Mx2N), warp 32x64, BK=16, 4 stages, 3 CTAs/SM.
// Grid 32x32 = 1024 tiles -> 6.92 tiles/SM -> ~1% wave-quantization loss.
constexpr int RBM = 64, RBN = 128;
constexpr int RABUF = RBM * ROWB;                      // 5120
constexpr int RBBUF = RBN * ROWB;                      // 10240
constexpr int RSMEM = STAGES * (RABUF + RBBUF);        // 61440

__global__ __launch_bounds__(128, 3)
void gemm_rec(const float* __restrict__ A,             // h read (ping-pong)
              const float* __restrict__ W,
              const float* __restrict__ Xg,
              float* __restrict__ hW, float* __restrict__ cP,
              float* __restrict__ yP, int writeY, int t)
{
    extern __shared__ float smem[];
    float (*sA)[RBM][BK + SPAD] = (float (*)[RBM][BK + SPAD])smem;
    float (*sB)[RBN][BK + SPAD] = (float (*)[RBN][BK + SPAD])(smem + STAGES * RBM * (BK + SPAD));
    const uint32_t sAb = (uint32_t)__cvta_generic_to_shared(&sA[0][0][0]);
    const uint32_t sBb = (uint32_t)__cvta_generic_to_shared(&sB[0][0][0]);

    const int tid  = threadIdx.x;
    const int bm   = blockIdx.y * RBM;
    const int bn   = blockIdx.x * RBN;
    const int ldr  = tid >> 2;          // 0..31
    const int ldc  = (tid & 3) * 4;
    const int K = HD, KT = HD / BK;     // 64

    const float* abase[2];
    const float* bbase[4];
#pragma unroll
    for (int i = 0; i < 2; ++i)
        abase[i] = A + (size_t)(bm + ldr + i * 32) * K + ldc;
#pragma unroll
    for (int i = 0; i < 4; ++i)
        bbase[i] = W + (size_t)(bn + ldr + i * 32) * K + ldc;

#pragma unroll
    for (int s = 0; s < STAGES - 1; ++s) {
#pragma unroll
        for (int i = 0; i < 2; ++i) cp16(&sA[s][ldr + i * 32][ldc], abase[i] + s * BK);
#pragma unroll
        for (int i = 0; i < 4; ++i) cp16(&sB[s][ldr + i * 32][ldc], bbase[i] + s * BK);
        CP_COMMIT();
    }

    const int wid  = tid >> 5;
    const int lane = tid & 31;
    const int wm   = (wid >> 1) * 32;   // 0,32
    const int wn   = (wid & 1) * 64;    // 0,64
    const int lr   = lane >> 2;
    const int lc   = lane & 3;

    const int lrowA = ((lane >> 3) & 1) * 8 + (lane & 7);
    const int lcolA = (lane >> 4) * 4;
    const int lrowB = (lane >> 4) * 8 + (lane & 7);
    const int lcolB = ((lane >> 3) & 1) * 4;
    const uint32_t aAddr0 = sAb + (uint32_t)((wm + lrowA) * ROWB + lcolA * 4);
    const uint32_t bAddr0 = sBb + (uint32_t)((wn + lrowB) * ROWB + lcolB * 4);

    float acc[2][8][4];
#pragma unroll
    for (int a = 0; a < 2; ++a)
#pragma unroll
        for (int b = 0; b < 8; ++b)
#pragma unroll
            for (int q = 0; q < 4; ++q) acc[a][b][q] = 0.f;

    for (int kt = 0; kt < KT; ++kt) {
        CP_WAIT(STAGES - 2);
        __syncthreads();
        const int buf = kt & (STAGES - 1);
        const uint32_t aS = aAddr0 + (uint32_t)(buf * RABUF);
        const uint32_t bS = bAddr0 + (uint32_t)(buf * RBBUF);

        const int pt = kt + STAGES - 1;
#pragma unroll
        for (int ks = 0; ks < 2; ++ks) {
            const uint32_t kOff = (uint32_t)(ks * 32);
            uint32_t af[2][4], bq[4][4];
#pragma unroll
            for (int mt = 0; mt < 2; ++mt) ldsm4(af[mt], aS + (uint32_t)(mt * 16 * ROWB) + kOff);
#pragma unroll
            for (int np = 0; np < 4; ++np) ldsm4(bq[np], bS + (uint32_t)(np * 16 * ROWB) + kOff);
            if (ks == 0) {           // prefetch next stage early, overlapped with MMAs
                if (pt < KT) {
                    const int ps = pt & (STAGES - 1);
#pragma unroll
                    for (int i = 0; i < 2; ++i) cp16(&sA[ps][ldr + i * 32][ldc], abase[i] + pt * BK);
#pragma unroll
                    for (int i = 0; i < 4; ++i) cp16(&sB[ps][ldr + i * 32][ldc], bbase[i] + pt * BK);
                }
                CP_COMMIT();
            }
#pragma unroll
            for (int mt = 0; mt < 2; ++mt)
#pragma unroll
                for (int nt = 0; nt < 8; ++nt)
                    mma_tf32(acc[mt][nt], af[mt], &bq[nt >> 1][(nt & 1) * 2]);
        }
    }

    // fused LSTM cell epilogue (t-major Xg/y rows)
#pragma unroll
    for (int mt = 0; mt < 2; ++mt) {
        const int gr0 = bm + wm + mt * 16 + lr;
        const int gr1 = gr0 + 8;
        const size_t xr0 = ((size_t)t * BATCH + gr0) * FOURH;
        const size_t xr1 = ((size_t)t * BATCH + gr1) * FOURH;
#pragma unroll
        for (int nt = 0; nt < 8; ++nt) {
            const int gc = bn + wn + nt * 8 + lc * 2;
            float2 x0 = *(const float2*)&Xg[xr0 + gc];
            float2 x1 = *(const float2*)&Xg[xr1 + gc];
            float v0 = acc[mt][nt][0] + x0.x;
            float v1 = acc[mt][nt][1] + x0.y;
            float v2 = acc[mt][nt][2] + x1.x;
            float v3 = acc[mt][nt][3] + x1.y;
            float p0 = __shfl_xor_sync(0xffffffffu, v0, 1);
            float p1 = __shfl_xor_sync(0xffffffffu, v1, 1);
            float p2 = __shfl_xor_sync(0xffffffffu, v2, 1);
            float p3 = __shfl_xor_sync(0xffffffffu, v3, 1);
            if ((lane & 1) == 0) {
                const int u = gc >> 2;
                const size_t cb0 = (size_t)gr0 * HD + u;
                const size_t cb1 = (size_t)gr1 * HD + u;
                float c0 = cP[cb0], c1 = cP[cb1];
                c0 = fsig(v1) * c0 + fsig(v0) * ftanh(p0);
                c1 = fsig(v3) * c1 + fsig(v2) * ftanh(p2);
                float h0 = fsig(p1) * ftanh(c0);
                float h1 = fsig(p3) * ftanh(c1);
                cP[cb0] = c0; cP[cb1] = c1;
                h0 = tf32r(h0); h1 = tf32r(h1);
                hW[cb0] = h0; hW[cb1] = h1;
                if (writeY) {
                    yP[((size_t)t * BATCH + gr0) * HD + u] = h0;
                    yP[((size_t)t * BATCH + gr1) * HD + u] = h1;
                }
            }
        }
    }
}

// ---------------- setup kernels ----------------
__global__ void permW_k(const float* __restrict__ in, float* __restrict__ out, int K)
{
    int idx = blockIdx.x * blockDim.x + threadIdx.x;
    if (idx < FOURH * K) {
        int rp = idx / K, k = idx - rp * K;
        int orig = (rp & 3) * HD + (rp >> 2);
        out[idx] = tf32r(in[orig * K + k]);
    }
}

__global__ void permB_k(const float* bi0, const float* bh0, const float* bi1, const float* bh1,
                        const float* bi2, const float* bh2, const float* bi3, const float* bh3,
                        float* __restrict__ out)
{
    int idx = blockIdx.x * blockDim.x + threadIdx.x;
    if (idx < 4 * FOURH) {
        int l = idx >> 12, rp = idx & (FOURH - 1);
        int orig = (rp & 3) * HD + (rp >> 2);
        const float* bi = (l == 0) ? bi0 : (l == 1) ? bi1 : (l == 2) ? bi2 : bi3;
        const float* bh = (l == 0) ? bh0 : (l == 1) ? bh1 : (l == 2) ? bh2 : bh3;
        out[idx] = bi[orig] + bh[orig];
    }
}

__global__ void embr_k(const float* __restrict__ emb, float* __restrict__ out)
{
    int i = blockIdx.x * blockDim.x + threadIdx.x;
    if (i < VOCAB * EDIM) out[i] = tf32r(emb[i]);
}

__global__ void zero_k(float* p, int n4)
{
    int i = blockIdx.x * blockDim.x + threadIdx.x;
    if (i < n4) ((float4*)p)[i] = make_float4(0.f, 0.f, 0.f, 0.f);
}

// t-major token arrays: r = t*BATCH + b
__global__ void build_tok_k(const int* __restrict__ src, const int* __restrict__ tgt,
                            int* __restrict__ srct, int* __restrict__ dect)
{
    int idx = blockIdx.x * blockDim.x + threadIdx.x;
    if (idx < MROWS) {
        int t = idx >> 11, b = idx & (BATCH - 1);
        srct[idx] = src[b * SEQ + t];
        dect[idx] = (t == 0) ? 1 : tgt[b * SEQ + t - 1];
    }
}

// ---------------- output projection (t-major y rows -> b-major out) ----------------
__global__ __launch_bounds__(256)
void proj_k(const float* __restrict__ y, const float* __restrict__ fcW,
            const float* __restrict__ fcb, float* __restrict__ out)
{
    __shared__ float ys[128][65];
    __shared__ float ws[40][65];
    const int tid = threadIdx.x;
    const int gm0 = blockIdx.x * 128;
    const int r0  = (tid >> 3) * 4;
    const int n0  = (tid & 7) * 5;

    float acc[4][5];
#pragma unroll
    for (int i = 0; i < 4; ++i)
#pragma unroll
        for (int j = 0; j < 5; ++j) acc[i][j] = 0.f;

    for (int kc = 0; kc < 16; ++kc) {
        __syncthreads();
        for (int i = tid; i < 128 * 16; i += 256) {
            int r = i >> 4, c4 = (i & 15) * 4;
            float4 v = *(const float4*)&y[(size_t)(gm0 + r) * HD + kc * 64 + c4];
            ys[r][c4] = v.x; ys[r][c4 + 1] = v.y; ys[r][c4 + 2] = v.z; ys[r][c4 + 3] = v.w;
        }
        for (int i = tid; i < 40 * 64; i += 256) {
            int n = i >> 6, cc = i & 63;
            ws[n][cc] = (n < VOCAB) ? fcW[n * HD + kc * 64 + cc] : 0.f;
        }
        __syncthreads();
#pragma unroll 8
        for (int k = 0; k < 64; ++k) {
            float yv[4], wv[5];
#pragma unroll
            for (int i = 0; i < 4; ++i) yv[i] = ys[r0 + i][k];
#pragma unroll
            for (int j = 0; j < 5; ++j) wv[j] = ws[n0 + j][k];
#pragma unroll
            for (int i = 0; i < 4; ++i)
#pragma unroll
                for (int j = 0; j < 5; ++j) acc[i][j] += yv[i] * wv[j];
        }
    }
#pragma unroll
    for (int i = 0; i < 4; ++i) {
        const int r = gm0 + r0 + i;
        const int b = r & (BATCH - 1), tt = r >> 11;
        const size_t ob = ((size_t)b * SEQ + tt) * VOCAB;
#pragma unroll
        for (int j = 0; j < 5; ++j) {
            int n = n0 + j;
            if (n < VOCAB) out[ob + n] = acc[i][j] + fcb[n];
        }
    }
}

// ---------------- host driver ----------------
extern "C" void kernel_launch(void* const* d_in, const int* in_sizes, int n_in,
                              void* d_out, int out_size)
{
    const int*   src    = (const int*)d_in[0];
    const int*   tgt    = (const int*)d_in[1];
    const float* emb    = (const float*)d_in[2];
    const float* eW_ih0 = (const float*)d_in[3];
    const float* eW_hh0 = (const float*)d_in[4];
    const float* eb_ih0 = (const float*)d_in[5];
    const float* eb_hh0 = (const float*)d_in[6];
    const float* eW_ih1 = (const float*)d_in[7];
    const float* eW_hh1 = (const float*)d_in[8];
    const float* eb_ih1 = (const float*)d_in[9];
    const float* eb_hh1 = (const float*)d_in[10];
    const float* dW_ih0 = (const float*)d_in[11];
    const float* dW_hh0 = (const float*)d_in[12];
    const float* db_ih0 = (const float*)d_in[13];
    const float* db_hh0 = (const float*)d_in[14];
    const float* dW_ih1 = (const float*)d_in[15];
    const float* dW_hh1 = (const float*)d_in[16];
    const float* db_ih1 = (const float*)d_in[17];
    const float* db_hh1 = (const float*)d_in[18];
    const float* fcW    = (const float*)d_in[19];
    const float* fcb    = (const float*)d_in[20];
    float* out = (float*)d_out;

    float *Xg, *y, *state, *wperm, *bsum, *embr;
    int *srct, *dect;
    cudaGetSymbolAddress((void**)&Xg,    g_Xg);
    cudaGetSymbolAddress((void**)&y,     g_y);
    cudaGetSymbolAddress((void**)&state, g_state);
    cudaGetSymbolAddress((void**)&wperm, g_wperm);
    cudaGetSymbolAddress((void**)&bsum,  g_bsum);
    cudaGetSymbolAddress((void**)&embr,  g_embr);
    cudaGetSymbolAddress((void**)&srct,  g_srct);
    cudaGetSymbolAddress((void**)&dect,  g_dect);

    cudaFuncSetAttribute(gemm_big, cudaFuncAttributeMaxDynamicSharedMemorySize, SMEM_BYTES);
    cudaFuncSetAttribute(gemm_rec, cudaFuncAttributeMaxDynamicSharedMemorySize, RSMEM);

    // h ping-pong buffers + c per layer
    float* h0buf[2] = { state,
                        state + (size_t)1 * BATCH * HD };
    float* c0      =   state + (size_t)2 * BATCH * HD;
    float* h1buf[2] = { state + (size_t)3 * BATCH * HD,
                        state + (size_t)4 * BATCH * HD };
    float* c1      =   state + (size_t)5 * BATCH * HD;

    size_t off = 0;
    float* eWih0p = wperm + off; off += (size_t)FOURH * EDIM;
    float* eWhh0p = wperm + off; off += (size_t)FOURH * HD;
    float* eWih1p = wperm + off; off += (size_t)FOURH * HD;
    float* eWhh1p = wperm + off; off += (size_t)FOURH * HD;
    float* dWih0p = wperm + off; off += (size_t)FOURH * EDIM;
    float* dWhh0p = wperm + off; off += (size_t)FOURH * HD;
    float* dWih1p = wperm + off; off += (size_t)FOURH * HD;
    float* dWhh1p = wperm + off; off += (size_t)FOURH * HD;

    // ---- setup ----
    {
        int nE = FOURH * EDIM, nH = FOURH * HD;
        permW_k<<<(nE + 255) / 256, 256>>>(eW_ih0, eWih0p, EDIM);
        permW_k<<<(nH + 255) / 256, 256>>>(eW_hh0, eWhh0p, HD);
        permW_k<<<(nH + 255) / 256, 256>>>(eW_ih1, eWih1p, HD);
        permW_k<<<(nH + 255) / 256, 256>>>(eW_hh1, eWhh1p, HD);
        permW_k<<<(nE + 255) / 256, 256>>>(dW_ih0, dWih0p, EDIM);
        permW_k<<<(nH + 255) / 256, 256>>>(dW_hh0, dWhh0p, HD);
        permW_k<<<(nH + 255) / 256, 256>>>(dW_ih1, dWih1p, HD);
        permW_k<<<(nH + 255) / 256, 256>>>(dW_hh1, dWhh1p, HD);
        permB_k<<<(4 * FOURH + 255) / 256, 256>>>(eb_ih0, eb_hh0, eb_ih1, eb_hh1,
                                                  db_ih0, db_hh0, db_ih1, db_hh1, bsum);
        embr_k<<<(VOCAB * EDIM + 255) / 256, 256>>>(emb, embr);
        int n4 = 6 * BATCH * HD / 4;
        zero_k<<<(n4 + 255) / 256, 256>>>(state, n4);
        build_tok_k<<<(MROWS + 255) / 256, 256>>>(src, tgt, srct, dect);
    }

    const dim3 gBig(FOURH / BN, MROWS / BM);    // (16, 384)
    const dim3 gRec(FOURH / RBN, BATCH / RBM);  // (32, 32) = 1024 tiles

    // ===== encoder layer 0 =====
    gemm_big<<<gBig, 256, SMEM_BYTES>>>(embr, srct, eWih0p, bsum + 0 * FOURH, Xg, EDIM);
    for (int t = 0; t < SEQ; ++t)
        gemm_rec<<<gRec, 128, RSMEM>>>(h0buf[t & 1], eWhh0p, Xg,
                                       h0buf[(t + 1) & 1], c0, y, 1, t);
    // ===== encoder layer 1 =====
    gemm_big<<<gBig, 256, SMEM_BYTES>>>(y, nullptr, eWih1p, bsum + 1 * FOURH, Xg, HD);
    for (int t = 0; t < SEQ; ++t)
        gemm_rec<<<gRec, 128, RSMEM>>>(h1buf[t & 1], eWhh1p, Xg,
                                       h1buf[(t + 1) & 1], c1, nullptr, 0, t);
    // ===== decoder layer 0 (SEQ even -> encoder-final h back in buf[0]) =====
    gemm_big<<<gBig, 256, SMEM_BYTES>>>(embr, dect, dWih0p, bsum + 2 * FOURH, Xg, EDIM);
    for (int t = 0; t < SEQ; ++t)
        gemm_rec<<<gRec, 128, RSMEM>>>(h0buf[t & 1], dWhh0p, Xg,
                                       h0buf[(t + 1) & 1], c0, y, 1, t);
    // ===== decoder layer 1 =====
    gemm_big<<<gBig, 256, SMEM_BYTES>>>(y, nullptr, dWih1p, bsum + 3 * FOURH, Xg, HD);
    for (int t = 0; t < SEQ; ++t)
        gemm_rec<<<gRec, 128, RSMEM>>>(h1buf[t & 1], dWhh1p, Xg,
                                       h1buf[(t + 1) & 1], c1, y, 1, t);
    // ===== output projection =====
    proj_k<<<MROWS / 128, 256>>>(y, fcW, fcb, out);
}